// round 6
// baseline (speedup 1.0000x reference)
#include <cuda_runtime.h>
#include <cuda_bf16.h>
#include <cstdint>

#define N_NODES 100000
#define N_EDGES 2048
#define L_TOK 8
#define HID 64
#define D_IN 512      // L_TOK * HID
#define D_GNN 128
#define VOCAB 32000
#define FFN_D 256
#define NROWS (N_EDGES * 2)   // 4096 lm-head rows
#define LBL_OFF 16384         // labels occupy [0, 16384)

// ---------------- device scratch (no allocations allowed) ----------------
__device__ float g_agg[N_NODES * D_GNN];    // only dst rows ever touched
__device__ float g_edge_h[N_EDGES * D_GNN];
__device__ float g_x[NROWS * HID];
__device__ float g_rowsum[NROWS];

// ---------------- K0: zero touched agg rows + row sums ----------------
__global__ void k0_zero(const int* __restrict__ edge_index) {
    int b = blockIdx.x, t = threadIdx.x;
    if (b < N_EDGES) {
        int dst = edge_index[N_EDGES + b];
        g_agg[dst * D_GNN + t] = 0.f;
    } else {
        int i = (b - N_EDGES) * 128 + t;
        if (i < NROWS) g_rowsum[i] = 0.f;
    }
}

// ---------------- K1: msg = (node_emb[src] + edge_emb) @ W_nbr; scatter-add at dst ----------------
__global__ void k1_msg(const int* __restrict__ node_tokens,
                       const int* __restrict__ edge_tokens,
                       const int* __restrict__ edge_index,
                       const float* __restrict__ emb,
                       const float* __restrict__ W_nbr) {
    __shared__ float t_s[16][D_IN];
    __shared__ int s_src[16], s_dst[16];
    int b = blockIdx.x, tid = threadIdx.x;
    int e0 = b * 16;
    if (tid < 16) {
        s_src[tid] = edge_index[e0 + tid];
        s_dst[tid] = edge_index[N_EDGES + e0 + tid];
    }
    __syncthreads();
    for (int el = 0; el < 16; el++) {
        int e = e0 + el;
        int sn = s_src[el];
        for (int idx = tid; idx < D_IN; idx += 128) {
            int l = idx >> 6, h = idx & 63;
            int tn = node_tokens[sn * L_TOK + l];
            int te = edge_tokens[e * L_TOK + l];
            t_s[el][idx] = emb[tn * HID + h] + emb[te * HID + h];
        }
    }
    __syncthreads();
    float acc[16];
#pragma unroll
    for (int el = 0; el < 16; el++) acc[el] = 0.f;
    for (int k = 0; k < D_IN; k++) {
        float w = W_nbr[k * D_GNN + tid];
#pragma unroll
        for (int el = 0; el < 16; el++) acc[el] += t_s[el][k] * w;
    }
#pragma unroll
    for (int el = 0; el < 16; el++)
        atomicAdd(&g_agg[s_dst[el] * D_GNN + tid], acc[el]);
}

// ---------------- K2: h = relu(node_emb @ W_self + agg) at endpoints; edge_h = h_src+h_dst ----------------
__global__ void k2_h(const int* __restrict__ node_tokens,
                     const int* __restrict__ edge_index,
                     const float* __restrict__ emb,
                     const float* __restrict__ W_self) {
    __shared__ float ne[16][D_IN];
    __shared__ int s_node[16];
    int b = blockIdx.x, tid = threadIdx.x;
    int e0 = b * 8;
    if (tid < 16) {
        int el = tid & 7;
        s_node[tid] = (tid < 8) ? edge_index[e0 + el] : edge_index[N_EDGES + e0 + el];
    }
    __syncthreads();
    for (int r = 0; r < 16; r++) {
        int n = s_node[r];
        for (int idx = tid; idx < D_IN; idx += 128) {
            int l = idx >> 6, h = idx & 63;
            int tn = node_tokens[n * L_TOK + l];
            ne[r][idx] = emb[tn * HID + h];
        }
    }
    __syncthreads();
    float acc[16];
#pragma unroll
    for (int r = 0; r < 16; r++) acc[r] = 0.f;
    for (int k = 0; k < D_IN; k++) {
        float w = W_self[k * D_GNN + tid];
#pragma unroll
        for (int r = 0; r < 16; r++) acc[r] += ne[r][k] * w;
    }
#pragma unroll
    for (int el = 0; el < 8; el++) {
        float hs = fmaxf(acc[el]     + g_agg[s_node[el]     * D_GNN + tid], 0.f);
        float hd = fmaxf(acc[el + 8] + g_agg[s_node[el + 8] * D_GNN + tid], 0.f);
        g_edge_h[(e0 + el) * D_GNN + tid] = hs + hd;
    }
}

// ---------------- K3: transformer block — warp per (edge,seq) row ----------------
__global__ __launch_bounds__(256) void k3_xform(const float* __restrict__ Wq, const float* __restrict__ Wk,
                                                const float* __restrict__ Wv, const float* __restrict__ Wo,
                                                const float* __restrict__ W1, const float* __restrict__ W2) {
    __shared__ float xsm[8][64];
    __shared__ float ksm[4][2][64];
    __shared__ float vsm[4][2][64];
    __shared__ float hsm[8][FFN_D];
    int tid = threadIdx.x, lane = tid & 31, wid = tid >> 5;
    int el = wid >> 1, s = wid & 1;
    int e = blockIdx.x * 4 + el;

    const float2* xg = (const float2*)g_edge_h;
    float2 xv = xg[e * 64 + s * 32 + lane];
    float x0 = xv.x, x1 = xv.y;
    xsm[wid][2 * lane] = x0;
    xsm[wid][2 * lane + 1] = x1;
    __syncwarp();

    const float2* Wq2 = (const float2*)Wq;
    const float2* Wk2 = (const float2*)Wk;
    const float2* Wv2 = (const float2*)Wv;
    const float2* Wo2 = (const float2*)Wo;
    const float2* W22 = (const float2*)W2;

    float q0 = 0.f, q1 = 0.f, kk0 = 0.f, kk1 = 0.f, v0 = 0.f, v1 = 0.f;
    float q0b = 0.f, q1b = 0.f, kk0b = 0.f, kk1b = 0.f, v0b = 0.f, v1b = 0.f;
#pragma unroll
    for (int k = 0; k < 64; k += 2) {
        float xa = xsm[wid][k], xb = xsm[wid][k + 1];
        float2 wqa = Wq2[k * 32 + lane], wqb = Wq2[(k + 1) * 32 + lane];
        float2 wka = Wk2[k * 32 + lane], wkb = Wk2[(k + 1) * 32 + lane];
        float2 wva = Wv2[k * 32 + lane], wvb = Wv2[(k + 1) * 32 + lane];
        q0 += xa * wqa.x; q1 += xa * wqa.y;
        kk0 += xa * wka.x; kk1 += xa * wka.y;
        v0 += xa * wva.x; v1 += xa * wva.y;
        q0b += xb * wqb.x; q1b += xb * wqb.y;
        kk0b += xb * wkb.x; kk1b += xb * wkb.y;
        v0b += xb * wvb.x; v1b += xb * wvb.y;
    }
    q0 += q0b; q1 += q1b; kk0 += kk0b; kk1 += kk1b; v0 += v0b; v1 += v1b;
    ksm[el][s][2 * lane] = kk0; ksm[el][s][2 * lane + 1] = kk1;
    vsm[el][s][2 * lane] = v0;  vsm[el][s][2 * lane + 1] = v1;
    __syncthreads();

    float p0 = q0 * ksm[el][0][2 * lane] + q1 * ksm[el][0][2 * lane + 1];
    float p1 = q0 * ksm[el][1][2 * lane] + q1 * ksm[el][1][2 * lane + 1];
#pragma unroll
    for (int d = 16; d; d >>= 1) {
        p0 += __shfl_xor_sync(0xffffffffu, p0, d);
        p1 += __shfl_xor_sync(0xffffffffu, p1, d);
    }
    p0 *= 0.125f; p1 *= 0.125f;
    float m = fmaxf(p0, p1);
    float ea = __expf(p0 - m), eb = __expf(p1 - m);
    float inv = 1.f / (ea + eb);
    float a0 = ea * inv, a1 = eb * inv;

    float y0 = a0 * vsm[el][0][2 * lane]     + a1 * vsm[el][1][2 * lane];
    float y1 = a0 * vsm[el][0][2 * lane + 1] + a1 * vsm[el][1][2 * lane + 1];

    xsm[wid][2 * lane] = y0;
    xsm[wid][2 * lane + 1] = y1;
    __syncwarp();

    float o0 = 0.f, o1 = 0.f, o0b = 0.f, o1b = 0.f;
#pragma unroll
    for (int k = 0; k < 64; k += 2) {
        float ya = xsm[wid][k], yb = xsm[wid][k + 1];
        float2 woa = Wo2[k * 32 + lane], wob = Wo2[(k + 1) * 32 + lane];
        o0 += ya * woa.x; o1 += ya * woa.y;
        o0b += yb * wob.x; o1b += yb * wob.y;
    }
    x0 += o0 + o0b; x1 += o1 + o1b;

    float msum = x0 + x1;
#pragma unroll
    for (int d = 16; d; d >>= 1) msum += __shfl_xor_sync(0xffffffffu, msum, d);
    float mean = msum * (1.f / 64.f);
    float d0 = x0 - mean, d1 = x1 - mean;
    float vsum = d0 * d0 + d1 * d1;
#pragma unroll
    for (int d = 16; d; d >>= 1) vsum += __shfl_xor_sync(0xffffffffu, vsum, d);
    float rstd = rsqrtf(vsum * (1.f / 64.f) + 1e-5f);
    x0 = d0 * rstd; x1 = d1 * rstd;

    __syncwarp();
    xsm[wid][2 * lane] = x0;
    xsm[wid][2 * lane + 1] = x1;
    __syncwarp();

    float h[8];
#pragma unroll
    for (int j = 0; j < 8; j++) h[j] = 0.f;
#pragma unroll 8
    for (int k = 0; k < 64; k++) {
        float xk = xsm[wid][k];
        const float* w1r = W1 + k * FFN_D + lane;
#pragma unroll
        for (int j = 0; j < 8; j++) h[j] += xk * w1r[j * 32];
    }
#pragma unroll
    for (int j = 0; j < 8; j++) hsm[wid][j * 32 + lane] = fmaxf(h[j], 0.f);
    __syncwarp();

    float o20 = 0.f, o21 = 0.f, o20b = 0.f, o21b = 0.f;
#pragma unroll 8
    for (int f = 0; f < FFN_D; f += 2) {
        float ha = hsm[wid][f], hb = hsm[wid][f + 1];
        float2 w2a = W22[f * 32 + lane], w2b = W22[(f + 1) * 32 + lane];
        o20 += ha * w2a.x; o21 += ha * w2a.y;
        o20b += hb * w2b.x; o21b += hb * w2b.y;
    }
    float z0 = x0 + o20 + o20b, z1 = x1 + o21 + o21b;

    msum = z0 + z1;
#pragma unroll
    for (int d = 16; d; d >>= 1) msum += __shfl_xor_sync(0xffffffffu, msum, d);
    mean = msum * (1.f / 64.f);
    d0 = z0 - mean; d1 = z1 - mean;
    vsum = d0 * d0 + d1 * d1;
#pragma unroll
    for (int d = 16; d; d >>= 1) vsum += __shfl_xor_sync(0xffffffffu, vsum, d);
    rstd = rsqrtf(vsum * (1.f / 64.f) + 1e-5f);
    float2* gx2 = (float2*)g_x;
    gx2[(e * 2 + s) * 32 + lane] = make_float2(d0 * rstd, d1 * rstd);
}

// ---------------- K4: lm head, bf16 mma.sync m16n8k16 — single pass: store exp + rowsum ----------------
// Fragment-major bf16x2 smem:
//   A: As[rt=8][ks=4][128 words]  word = bf16x2(k even/odd); within: half*64 + g*8 + tg*2 + hi
//   B: Bs[nt=16][ks=4][64 words]  within: g*8 + tg*2 + hi
// Warp grid 4x2: warp wm,wn -> rows wm*32..+31, cols wn*64..+63.
#define SMEM_K4 ((4096 + 4096 + 128) * 4)

__device__ __forceinline__ uint32_t pack_bf16x2(float lo, float hi) {
    __nv_bfloat162 b = __float22bfloat162_rn(make_float2(lo, hi));
    return *(uint32_t*)&b;
}

__global__ __launch_bounds__(256) void k4_tc(const float* __restrict__ lmW,
                                             const float* __restrict__ lmb,
                                             float* __restrict__ out) {
    extern __shared__ uint32_t dsm[];
    uint32_t* As = dsm;             // 4096 words
    uint32_t* Bs = dsm + 4096;      // 4096 words
    float* bsm = (float*)(dsm + 8192);

    int tid = threadIdx.x;
    int cb = blockIdx.x * 128, rb = blockIdx.y * 128;

    // A fill: 128 rows x 32 kpairs
    const float2* gx2 = (const float2*)g_x;
    for (int i = tid; i < 4096; i += 256) {
        int r = i >> 5, w = i & 31;                 // w = kpair index (k = 2w, 2w+1)
        float2 v = gx2[(size_t)(rb + r) * 32 + w];
        int rt = r >> 4, r16 = r & 15, half = r16 >> 3, gg = r16 & 7;
        int ks = w >> 3, pr = w & 7, hi = pr >> 2, tg = pr & 3;
        As[(rt * 4 + ks) * 128 + half * 64 + gg * 8 + tg * 2 + hi] = pack_bf16x2(v.x, v.y);
    }
    // B fill: 128 cols x 32 kpairs (two strided global rows per word; coalesced over n)
    for (int i = tid; i < 4096; i += 256) {
        int n = i & 127, w = i >> 7;
        float v0 = lmW[(size_t)(2 * w) * VOCAB + cb + n];
        float v1 = lmW[(size_t)(2 * w + 1) * VOCAB + cb + n];
        int nt = n >> 3, gg = n & 7;
        int ks = w >> 3, pr = w & 7, hi = pr >> 2, tg = pr & 3;
        Bs[(nt * 4 + ks) * 64 + gg * 8 + tg * 2 + hi] = pack_bf16x2(v0, v1);
    }
    if (tid < 128) bsm[tid] = lmb[cb + tid];
    __syncthreads();

    int lane = tid & 31, warp = tid >> 5;
    int wm = warp >> 1, wn = warp & 1;
    int g = lane >> 2, tig = lane & 3;

    float acc[2][8][4];
#pragma unroll
    for (int mt = 0; mt < 2; mt++)
#pragma unroll
        for (int nt = 0; nt < 8; nt++)
#pragma unroll
            for (int j = 0; j < 4; j++) acc[mt][nt][j] = 0.f;

#pragma unroll
    for (int ks = 0; ks < 4; ks++) {
        uint32_t a[2][4];
#pragma unroll
        for (int mt = 0; mt < 2; mt++) {
            const uint32_t* ap = As + ((wm * 2 + mt) * 4 + ks) * 128;
            uint2 p0 = *(const uint2*)(ap + lane * 2);        // a0 (row g, pair tig), a2 (row g, pair tig+4)
            uint2 p1 = *(const uint2*)(ap + 64 + lane * 2);   // a1 (row g+8, ...), a3
            a[mt][0] = p0.x; a[mt][2] = p0.y; a[mt][1] = p1.x; a[mt][3] = p1.y;
        }
#pragma unroll
        for (int nt = 0; nt < 8; nt++) {
            const uint32_t* bp = Bs + ((wn * 8 + nt) * 4 + ks) * 64;
            uint2 bb = *(const uint2*)(bp + lane * 2);        // b0 (k 2tig.., col g), b1 (k 8+2tig..)
#pragma unroll
            for (int mt = 0; mt < 2; mt++) {
                asm volatile(
                    "mma.sync.aligned.m16n8k16.row.col.f32.bf16.bf16.f32 "
                    "{%0,%1,%2,%3}, {%4,%5,%6,%7}, {%8,%9}, {%0,%1,%2,%3};\n"
                    : "+f"(acc[mt][nt][0]), "+f"(acc[mt][nt][1]),
                      "+f"(acc[mt][nt][2]), "+f"(acc[mt][nt][3])
                    : "r"(a[mt][0]), "r"(a[mt][1]), "r"(a[mt][2]), "r"(a[mt][3]),
                      "r"(bb.x), "r"(bb.y));
            }
        }
    }

    // epilogue: exp + store (unnormalized) + rowsum atomics
#pragma unroll
    for (int mt = 0; mt < 2; mt++) {
        int r_lo = rb + wm * 32 + mt * 16 + g, r_hi = r_lo + 8;
        float slo = 0.f, shi = 0.f;
#pragma unroll
        for (int nt = 0; nt < 8; nt++) {
            int c = wn * 64 + nt * 8 + 2 * tig;
            float b0v = bsm[c], b1v = bsm[c + 1];
            float e0 = __expf(acc[mt][nt][0] + b0v);
            float e1 = __expf(acc[mt][nt][1] + b1v);
            float e2 = __expf(acc[mt][nt][2] + b0v);
            float e3 = __expf(acc[mt][nt][3] + b1v);
            slo += e0 + e1;
            shi += e2 + e3;
            size_t base = (size_t)LBL_OFF + (size_t)cb + c;
            *(float2*)&out[base + (size_t)r_lo * VOCAB] = make_float2(e0, e1);
            *(float2*)&out[base + (size_t)r_hi * VOCAB] = make_float2(e2, e3);
        }
        slo += __shfl_xor_sync(0xffffffffu, slo, 1);
        slo += __shfl_xor_sync(0xffffffffu, slo, 2);
        shi += __shfl_xor_sync(0xffffffffu, shi, 1);
        shi += __shfl_xor_sync(0xffffffffu, shi, 2);
        if (tig == 0) {
            atomicAdd(&g_rowsum[r_lo], slo);
            atomicAdd(&g_rowsum[r_hi], shi);
        }
    }
}

// ---------------- K5: in-place normalization (float4 RMW) ----------------
__global__ __launch_bounds__(256) void k5_norm(float* __restrict__ out) {
    int row = blockIdx.x;
    float inv = 1.f / g_rowsum[row];
    float4* p = (float4*)(out + (size_t)LBL_OFF + (size_t)row * VOCAB);
    for (int i = threadIdx.x; i < VOCAB / 4; i += 256) {
        float4 v = p[i];
        v.x *= inv; v.y *= inv; v.z *= inv; v.w *= inv;
        p[i] = v;
    }
}

// ---------------- K6: labels ----------------
__global__ void k6_labels(const int* __restrict__ edge_tokens, float* __restrict__ out) {
    int idx = blockIdx.x * 256 + threadIdx.x;
    if (idx < N_EDGES * L_TOK) {
        int e = idx >> 3;
        int tok = edge_tokens[idx];
        int lab = (e == 0 && tok >= 4) ? tok : -100;
        out[idx] = (float)lab;
    }
}

// ---------------- launch ----------------
extern "C" void kernel_launch(void* const* d_in, const int* in_sizes, int n_in,
                              void* d_out, int out_size) {
    const int*   node_tokens = (const int*)d_in[0];
    const int*   edge_tokens = (const int*)d_in[1];
    const int*   edge_index  = (const int*)d_in[2];
    const float* emb    = (const float*)d_in[3];
    const float* W_self = (const float*)d_in[4];
    const float* W_nbr  = (const float*)d_in[5];
    const float* Wq     = (const float*)d_in[6];
    const float* Wk     = (const float*)d_in[7];
    const float* Wv     = (const float*)d_in[8];
    const float* Wo     = (const float*)d_in[9];
    const float* W1     = (const float*)d_in[10];
    const float* W2     = (const float*)d_in[11];
    const float* lmW    = (const float*)d_in[12];
    const float* lmb    = (const float*)d_in[13];
    float* out = (float*)d_out;

    k0_zero<<<2080, 128>>>(edge_index);
    k1_msg<<<128, 128>>>(node_tokens, edge_tokens, edge_index, emb, W_nbr);
    k2_h<<<256, 128>>>(node_tokens, edge_index, emb, W_self);
    k3_xform<<<512, 256>>>(Wq, Wk, Wv, Wo, W1, W2);
    k4_tc<<<dim3(250, 32), 256, SMEM_K4>>>(lmW, lmb, out);
    k5_norm<<<4096, 256>>>(out);
    k6_labels<<<64, 256>>>(edge_tokens, out);
}

// round 7
// speedup vs baseline: 1.1411x; 1.1411x over previous
#include <cuda_runtime.h>
#include <cstdint>

#define N_NODES 100000
#define N_EDGES 2048
#define L_TOK 8
#define HID 64
#define D_IN 512      // L_TOK * HID
#define D_GNN 128
#define VOCAB 32000
#define FFN_D 256
#define NROWS (N_EDGES * 2)   // 4096 lm-head rows
#define LBL_OFF 16384         // labels occupy [0, 16384)

// ---------------- device scratch (no allocations allowed) ----------------
__device__ float g_agg[N_NODES * D_GNN];    // only dst rows ever touched
__device__ float g_x[NROWS * HID];
__device__ float g_rowsum[NROWS];

// ---------------- K0: zero touched agg rows + row sums ----------------
__global__ void k0_zero(const int* __restrict__ edge_index) {
    int b = blockIdx.x, t = threadIdx.x;
    if (b < N_EDGES) {
        int dst = edge_index[N_EDGES + b];
        g_agg[dst * D_GNN + t] = 0.f;
    } else {
        int i = (b - N_EDGES) * 128 + t;
        if (i < NROWS) g_rowsum[i] = 0.f;
    }
}

// ---------------- K1: msg = (node_emb[src] + edge_emb) @ W_nbr; scatter-add at dst ----------------
__global__ void k1_msg(const int* __restrict__ node_tokens,
                       const int* __restrict__ edge_tokens,
                       const int* __restrict__ edge_index,
                       const float* __restrict__ emb,
                       const float* __restrict__ W_nbr) {
    __shared__ float t_s[16][D_IN];
    __shared__ int s_src[16], s_dst[16];
    int b = blockIdx.x, tid = threadIdx.x;
    int e0 = b * 16;
    if (tid < 16) {
        s_src[tid] = edge_index[e0 + tid];
        s_dst[tid] = edge_index[N_EDGES + e0 + tid];
    }
    __syncthreads();
    for (int el = 0; el < 16; el++) {
        int e = e0 + el;
        int sn = s_src[el];
        for (int idx = tid; idx < D_IN; idx += 128) {
            int l = idx >> 6, h = idx & 63;
            int tn = node_tokens[sn * L_TOK + l];
            int te = edge_tokens[e * L_TOK + l];
            t_s[el][idx] = emb[tn * HID + h] + emb[te * HID + h];
        }
    }
    __syncthreads();
    float acc[16];
#pragma unroll
    for (int el = 0; el < 16; el++) acc[el] = 0.f;
    for (int k = 0; k < D_IN; k++) {
        float w = W_nbr[k * D_GNN + tid];
#pragma unroll
        for (int el = 0; el < 16; el++) acc[el] += t_s[el][k] * w;
    }
#pragma unroll
    for (int el = 0; el < 16; el++)
        atomicAdd(&g_agg[s_dst[el] * D_GNN + tid], acc[el]);
}

// ---------------- K3: fused (k2 + transformer): h at endpoints, edge_h, xform ----------------
__global__ __launch_bounds__(256) void k3_fused(const int* __restrict__ node_tokens,
                                                const int* __restrict__ edge_index,
                                                const float* __restrict__ emb,
                                                const float* __restrict__ W_self,
                                                const float* __restrict__ Wq, const float* __restrict__ Wk,
                                                const float* __restrict__ Wv, const float* __restrict__ Wo,
                                                const float* __restrict__ W1, const float* __restrict__ W2) {
    __shared__ float ne[8][D_IN];      // endpoint embeddings (16 KB)
    __shared__ float hn[8][D_GNN];     // endpoint GNN outputs (4 KB)
    __shared__ int snode[8];
    __shared__ float xsm[8][64];
    __shared__ float ksm[4][2][64];
    __shared__ float vsm[4][2][64];
    __shared__ float hsm[8][FFN_D];

    int tid = threadIdx.x, lane = tid & 31, wid = tid >> 5;
    int e_base = blockIdx.x * 4;

    // ---- endpoint node ids: slot j = edge (j>>1), src/dst (j&1) ----
    if (tid < 8)
        snode[tid] = edge_index[(tid & 1) * N_EDGES + e_base + (tid >> 1)];
    __syncthreads();

    // ---- gather embeddings ----
    for (int idx = tid; idx < 8 * D_IN; idx += 256) {
        int j = idx >> 9, kk = idx & 511;
        int l = kk >> 6, hcol = kk & 63;
        int tok = node_tokens[snode[j] * L_TOK + l];
        ne[j][kk] = emb[tok * HID + hcol];
    }
    __syncthreads();

    // ---- h = relu(emb @ W_self + agg): group (tid>>7) owns 4 nodes, thread owns col c ----
    {
        int c = tid & 127, grp = tid >> 7;
        float acc0 = 0.f, acc1 = 0.f, acc2 = 0.f, acc3 = 0.f;
        const float4* n0 = (const float4*)ne[grp * 4 + 0];
        const float4* n1 = (const float4*)ne[grp * 4 + 1];
        const float4* n2 = (const float4*)ne[grp * 4 + 2];
        const float4* n3 = (const float4*)ne[grp * 4 + 3];
#pragma unroll 4
        for (int k4i = 0; k4i < D_IN / 4; k4i++) {
            float4 a = n0[k4i], b = n1[k4i], cc = n2[k4i], d = n3[k4i];
            const float* wr = W_self + k4i * 4 * D_GNN + c;
            float w0 = wr[0], w1 = wr[D_GNN], w2 = wr[2 * D_GNN], w3 = wr[3 * D_GNN];
            acc0 += a.x * w0 + a.y * w1 + a.z * w2 + a.w * w3;
            acc1 += b.x * w0 + b.y * w1 + b.z * w2 + b.w * w3;
            acc2 += cc.x * w0 + cc.y * w1 + cc.z * w2 + cc.w * w3;
            acc3 += d.x * w0 + d.y * w1 + d.z * w2 + d.w * w3;
        }
        hn[grp * 4 + 0][c] = fmaxf(acc0 + g_agg[snode[grp * 4 + 0] * D_GNN + c], 0.f);
        hn[grp * 4 + 1][c] = fmaxf(acc1 + g_agg[snode[grp * 4 + 1] * D_GNN + c], 0.f);
        hn[grp * 4 + 2][c] = fmaxf(acc2 + g_agg[snode[grp * 4 + 2] * D_GNN + c], 0.f);
        hn[grp * 4 + 3][c] = fmaxf(acc3 + g_agg[snode[grp * 4 + 3] * D_GNN + c], 0.f);
    }
    __syncthreads();

    // ---- transformer: warp per (edge el = wid>>1, seq s = wid&1) ----
    int el = wid >> 1, s = wid & 1;
    int e = e_base + el;

    const float2* hs2 = (const float2*)&hn[2 * el][s * 64];
    const float2* hd2 = (const float2*)&hn[2 * el + 1][s * 64];
    float2 xa2 = hs2[lane], xb2 = hd2[lane];
    float x0 = xa2.x + xb2.x, x1 = xa2.y + xb2.y;
    xsm[wid][2 * lane] = x0;
    xsm[wid][2 * lane + 1] = x1;
    __syncwarp();

    const float2* Wq2 = (const float2*)Wq;
    const float2* Wk2 = (const float2*)Wk;
    const float2* Wv2 = (const float2*)Wv;
    const float2* Wo2 = (const float2*)Wo;
    const float2* W22 = (const float2*)W2;

    float q0 = 0.f, q1 = 0.f, kk0 = 0.f, kk1 = 0.f, v0 = 0.f, v1 = 0.f;
    float q0b = 0.f, q1b = 0.f, kk0b = 0.f, kk1b = 0.f, v0b = 0.f, v1b = 0.f;
#pragma unroll
    for (int k = 0; k < 64; k += 2) {
        float xa = xsm[wid][k], xb = xsm[wid][k + 1];
        float2 wqa = Wq2[k * 32 + lane], wqb = Wq2[(k + 1) * 32 + lane];
        float2 wka = Wk2[k * 32 + lane], wkb = Wk2[(k + 1) * 32 + lane];
        float2 wva = Wv2[k * 32 + lane], wvb = Wv2[(k + 1) * 32 + lane];
        q0 += xa * wqa.x; q1 += xa * wqa.y;
        kk0 += xa * wka.x; kk1 += xa * wka.y;
        v0 += xa * wva.x; v1 += xa * wva.y;
        q0b += xb * wqb.x; q1b += xb * wqb.y;
        kk0b += xb * wkb.x; kk1b += xb * wkb.y;
        v0b += xb * wvb.x; v1b += xb * wvb.y;
    }
    q0 += q0b; q1 += q1b; kk0 += kk0b; kk1 += kk1b; v0 += v0b; v1 += v1b;
    ksm[el][s][2 * lane] = kk0; ksm[el][s][2 * lane + 1] = kk1;
    vsm[el][s][2 * lane] = v0;  vsm[el][s][2 * lane + 1] = v1;
    __syncthreads();

    float p0 = q0 * ksm[el][0][2 * lane] + q1 * ksm[el][0][2 * lane + 1];
    float p1 = q0 * ksm[el][1][2 * lane] + q1 * ksm[el][1][2 * lane + 1];
#pragma unroll
    for (int d = 16; d; d >>= 1) {
        p0 += __shfl_xor_sync(0xffffffffu, p0, d);
        p1 += __shfl_xor_sync(0xffffffffu, p1, d);
    }
    p0 *= 0.125f; p1 *= 0.125f;
    float m = fmaxf(p0, p1);
    float ea = __expf(p0 - m), eb = __expf(p1 - m);
    float inv = 1.f / (ea + eb);
    float a0 = ea * inv, a1 = eb * inv;

    float y0 = a0 * vsm[el][0][2 * lane]     + a1 * vsm[el][1][2 * lane];
    float y1 = a0 * vsm[el][0][2 * lane + 1] + a1 * vsm[el][1][2 * lane + 1];

    xsm[wid][2 * lane] = y0;
    xsm[wid][2 * lane + 1] = y1;
    __syncwarp();

    float o0 = 0.f, o1 = 0.f, o0b = 0.f, o1b = 0.f;
#pragma unroll
    for (int k = 0; k < 64; k += 2) {
        float ya = xsm[wid][k], yb = xsm[wid][k + 1];
        float2 woa = Wo2[k * 32 + lane], wob = Wo2[(k + 1) * 32 + lane];
        o0 += ya * woa.x; o1 += ya * woa.y;
        o0b += yb * wob.x; o1b += yb * wob.y;
    }
    x0 += o0 + o0b; x1 += o1 + o1b;

    float msum = x0 + x1;
#pragma unroll
    for (int d = 16; d; d >>= 1) msum += __shfl_xor_sync(0xffffffffu, msum, d);
    float mean = msum * (1.f / 64.f);
    float d0 = x0 - mean, d1 = x1 - mean;
    float vsum = d0 * d0 + d1 * d1;
#pragma unroll
    for (int d = 16; d; d >>= 1) vsum += __shfl_xor_sync(0xffffffffu, vsum, d);
    float rstd = rsqrtf(vsum * (1.f / 64.f) + 1e-5f);
    x0 = d0 * rstd; x1 = d1 * rstd;

    __syncwarp();
    xsm[wid][2 * lane] = x0;
    xsm[wid][2 * lane + 1] = x1;
    __syncwarp();

    float h[8];
#pragma unroll
    for (int j = 0; j < 8; j++) h[j] = 0.f;
#pragma unroll 8
    for (int k = 0; k < 64; k++) {
        float xk = xsm[wid][k];
        const float* w1r = W1 + k * FFN_D + lane;
#pragma unroll
        for (int j = 0; j < 8; j++) h[j] += xk * w1r[j * 32];
    }
#pragma unroll
    for (int j = 0; j < 8; j++) hsm[wid][j * 32 + lane] = fmaxf(h[j], 0.f);
    __syncwarp();

    float o20 = 0.f, o21 = 0.f, o20b = 0.f, o21b = 0.f;
#pragma unroll 8
    for (int f = 0; f < FFN_D; f += 2) {
        float ha = hsm[wid][f], hb = hsm[wid][f + 1];
        float2 w2a = W22[f * 32 + lane], w2b = W22[(f + 1) * 32 + lane];
        o20 += ha * w2a.x; o21 += ha * w2a.y;
        o20b += hb * w2b.x; o21b += hb * w2b.y;
    }
    float z0 = x0 + o20 + o20b, z1 = x1 + o21 + o21b;

    msum = z0 + z1;
#pragma unroll
    for (int d = 16; d; d >>= 1) msum += __shfl_xor_sync(0xffffffffu, msum, d);
    mean = msum * (1.f / 64.f);
    d0 = z0 - mean; d1 = z1 - mean;
    vsum = d0 * d0 + d1 * d1;
#pragma unroll
    for (int d = 16; d; d >>= 1) vsum += __shfl_xor_sync(0xffffffffu, vsum, d);
    rstd = rsqrtf(vsum * (1.f / 64.f) + 1e-5f);
    float2* gx2 = (float2*)g_x;
    gx2[(e * 2 + s) * 32 + lane] = make_float2(d0 * rstd, d1 * rstd);
}

// ---------------- K4: lm head, tf32 mma.sync, B-resident row loop ----------------
// Grid (250, 4): block owns 128 cols (B loaded once) x 8 row-tiles of 128.
// A frags: As[rt8=8][ks=8][128]; B frags: Bs[nt=16][ks=8][64]; warp grid 4x2.
#define SMEM_K4 ((8192 + 8192 + 128) * 4)
#define K4_ROW_ITERS 8

__global__ __launch_bounds__(256) void k4_tc(const float* __restrict__ lmW,
                                             const float* __restrict__ lmb,
                                             float* __restrict__ out) {
    extern __shared__ uint32_t dsm[];
    uint32_t* As = dsm;
    uint32_t* Bs = dsm + 8192;
    float* bsm = (float*)(dsm + 16384);

    int tid = threadIdx.x;
    int cb = blockIdx.x * 128;

    // ---- B + bias fill (once per block) ----
    for (int i = tid; i < 8192; i += 256) {
        int n = i & 127, k = i >> 7;
        float v = lmW[(size_t)k * VOCAB + cb + n];
        uint32_t u; asm("cvt.rna.tf32.f32 %0, %1;" : "=r"(u) : "f"(v));
        int nt = n >> 3, gg = n & 7, ks = k >> 3, k8 = k & 7, hi = k8 >> 2, tg = k8 & 3;
        Bs[(nt * 8 + ks) * 64 + gg * 8 + tg * 2 + hi] = u;
    }
    if (tid < 128) bsm[tid] = lmb[cb + tid];

    int lane = tid & 31, warp = tid >> 5;
    int wm = warp >> 1, wn = warp & 1;
    int g = lane >> 2, tig = lane & 3;

    for (int it = 0; it < K4_ROW_ITERS; it++) {
        int rb = (blockIdx.y * K4_ROW_ITERS + it) * 128;
        __syncthreads();   // B ready (first iter) / prev-iter A consumers done
        // ---- A fill ----
        for (int i = tid; i < 8192; i += 256) {
            int r = i >> 6, k = i & 63;
            float v = g_x[(rb + r) * 64 + k];
            uint32_t u; asm("cvt.rna.tf32.f32 %0, %1;" : "=r"(u) : "f"(v));
            int rt = r >> 4, r16 = r & 15, half = r16 >> 3, gg = r16 & 7;
            int ks = k >> 3, k8 = k & 7, hi = k8 >> 2, tg = k8 & 3;
            As[(rt * 8 + ks) * 128 + half * 64 + gg * 8 + tg * 2 + hi] = u;
        }
        __syncthreads();

        float acc[2][8][4];
#pragma unroll
        for (int mt = 0; mt < 2; mt++)
#pragma unroll
            for (int nt = 0; nt < 8; nt++)
#pragma unroll
                for (int j = 0; j < 4; j++) acc[mt][nt][j] = 0.f;

#pragma unroll
        for (int ks = 0; ks < 8; ks++) {
            uint32_t a[2][4];
#pragma unroll
            for (int mt = 0; mt < 2; mt++) {
                const uint32_t* ap = As + ((wm * 2 + mt) * 8 + ks) * 128;
                uint2 p0 = *(const uint2*)(ap + lane * 2);
                uint2 p1 = *(const uint2*)(ap + 64 + lane * 2);
                a[mt][0] = p0.x; a[mt][2] = p0.y; a[mt][1] = p1.x; a[mt][3] = p1.y;
            }
#pragma unroll
            for (int nt = 0; nt < 8; nt++) {
                const uint32_t* bp = Bs + ((wn * 8 + nt) * 8 + ks) * 64;
                uint2 bb = *(const uint2*)(bp + lane * 2);
#pragma unroll
                for (int mt = 0; mt < 2; mt++) {
                    asm volatile(
                        "mma.sync.aligned.m16n8k8.row.col.f32.tf32.tf32.f32 "
                        "{%0,%1,%2,%3}, {%4,%5,%6,%7}, {%8,%9}, {%0,%1,%2,%3};\n"
                        : "+f"(acc[mt][nt][0]), "+f"(acc[mt][nt][1]),
                          "+f"(acc[mt][nt][2]), "+f"(acc[mt][nt][3])
                        : "r"(a[mt][0]), "r"(a[mt][1]), "r"(a[mt][2]), "r"(a[mt][3]),
                          "r"(bb.x), "r"(bb.y));
                }
            }
        }

        // ---- epilogue: exp + store (unnormalized) + rowsum atomics ----
#pragma unroll
        for (int mt = 0; mt < 2; mt++) {
            int r_lo = rb + wm * 32 + mt * 16 + g, r_hi = r_lo + 8;
            float slo = 0.f, shi = 0.f;
#pragma unroll
            for (int nt = 0; nt < 8; nt++) {
                int c = wn * 64 + nt * 8 + 2 * tig;
                float b0v = bsm[c], b1v = bsm[c + 1];
                float e0 = __expf(acc[mt][nt][0] + b0v);
                float e1 = __expf(acc[mt][nt][1] + b1v);
                float e2 = __expf(acc[mt][nt][2] + b0v);
                float e3 = __expf(acc[mt][nt][3] + b1v);
                slo += e0 + e1;
                shi += e2 + e3;
                size_t base = (size_t)LBL_OFF + (size_t)cb + c;
                *(float2*)&out[base + (size_t)r_lo * VOCAB] = make_float2(e0, e1);
                *(float2*)&out[base + (size_t)r_hi * VOCAB] = make_float2(e2, e3);
            }
            slo += __shfl_xor_sync(0xffffffffu, slo, 1);
            slo += __shfl_xor_sync(0xffffffffu, slo, 2);
            shi += __shfl_xor_sync(0xffffffffu, shi, 1);
            shi += __shfl_xor_sync(0xffffffffu, shi, 2);
            if (tig == 0) {
                atomicAdd(&g_rowsum[r_lo], slo);
                atomicAdd(&g_rowsum[r_hi], shi);
            }
        }
    }
}

// ---------------- K5: in-place normalization (float4 RMW) ----------------
__global__ __launch_bounds__(512) void k5_norm(float* __restrict__ out) {
    int row = blockIdx.x;
    float inv = 1.f / g_rowsum[row];
    float4* p = (float4*)(out + (size_t)LBL_OFF + (size_t)row * VOCAB);
    for (int i = threadIdx.x; i < VOCAB / 4; i += 512) {
        float4 v = p[i];
        v.x *= inv; v.y *= inv; v.z *= inv; v.w *= inv;
        p[i] = v;
    }
}

// ---------------- K6: labels ----------------
__global__ void k6_labels(const int* __restrict__ edge_tokens, float* __restrict__ out) {
    int idx = blockIdx.x * 256 + threadIdx.x;
    if (idx < N_EDGES * L_TOK) {
        int e = idx >> 3;
        int tok = edge_tokens[idx];
        int lab = (e == 0 && tok >= 4) ? tok : -100;
        out[idx] = (float)lab;
    }
}

// ---------------- launch ----------------
extern "C" void kernel_launch(void* const* d_in, const int* in_sizes, int n_in,
                              void* d_out, int out_size) {
    const int*   node_tokens = (const int*)d_in[0];
    const int*   edge_tokens = (const int*)d_in[1];
    const int*   edge_index  = (const int*)d_in[2];
    const float* emb    = (const float*)d_in[3];
    const float* W_self = (const float*)d_in[4];
    const float* W_nbr  = (const float*)d_in[5];
    const float* Wq     = (const float*)d_in[6];
    const float* Wk     = (const float*)d_in[7];
    const float* Wv     = (const float*)d_in[8];
    const float* Wo     = (const float*)d_in[9];
    const float* W1     = (const float*)d_in[10];
    const float* W2     = (const float*)d_in[11];
    const float* lmW    = (const float*)d_in[12];
    const float* lmb    = (const float*)d_in[13];
    float* out = (float*)d_out;

    cudaFuncSetAttribute(k4_tc, cudaFuncAttributeMaxDynamicSharedMemorySize, SMEM_K4);

    k0_zero<<<2080, 128>>>(edge_index);
    k1_msg<<<128, 128>>>(node_tokens, edge_tokens, edge_index, emb, W_nbr);
    k3_fused<<<512, 256>>>(node_tokens, edge_index, emb, W_self,
                           Wq, Wk, Wv, Wo, W1, W2);
    k4_tc<<<dim3(250, 4), 256, SMEM_K4>>>(lmW, lmb, out);
    k5_norm<<<4096, 512>>>(out);
    k6_labels<<<64, 256>>>(edge_tokens, out);
}

// round 8
// speedup vs baseline: 1.3516x; 1.1845x over previous
#include <cuda_runtime.h>
#include <cstdint>

#define N_NODES 100000
#define N_EDGES 2048
#define L_TOK 8
#define HID 64
#define D_IN 512      // L_TOK * HID
#define D_GNN 128
#define VOCAB 32000
#define FFN_D 256
#define NROWS (N_EDGES * 2)   // 4096 lm-head rows
#define LBL_OFF 16384         // labels occupy [0, 16384)

// ---------------- device scratch (no allocations allowed) ----------------
__device__ float g_agg[N_NODES * D_GNN];          // only dst rows ever touched
__device__ uint32_t g_xf[256 * 8 * 128];          // x in tf32 fragment-major: [rt16][ks][word]
__device__ float g_rowsum[NROWS];

// ---------------- K0: zero touched agg rows + row sums ----------------
__global__ void k0_zero(const int* __restrict__ edge_index) {
    int b = blockIdx.x, t = threadIdx.x;
    if (b < N_EDGES) {
        int dst = edge_index[N_EDGES + b];
        g_agg[dst * D_GNN + t] = 0.f;
    } else {
        int i = (b - N_EDGES) * 128 + t;
        if (i < NROWS) g_rowsum[i] = 0.f;
    }
}

// ---------------- K1: msg = (node_emb[src] + edge_emb) @ W_nbr; scatter-add at dst ----------------
__global__ void k1_msg(const int* __restrict__ node_tokens,
                       const int* __restrict__ edge_tokens,
                       const int* __restrict__ edge_index,
                       const float* __restrict__ emb,
                       const float* __restrict__ W_nbr) {
    __shared__ float t_s[16][D_IN];
    __shared__ int s_src[16], s_dst[16];
    int b = blockIdx.x, tid = threadIdx.x;
    int e0 = b * 16;
    if (tid < 16) {
        s_src[tid] = edge_index[e0 + tid];
        s_dst[tid] = edge_index[N_EDGES + e0 + tid];
    }
    __syncthreads();
    for (int el = 0; el < 16; el++) {
        int e = e0 + el;
        int sn = s_src[el];
        for (int idx = tid; idx < D_IN; idx += 128) {
            int l = idx >> 6, h = idx & 63;
            int tn = node_tokens[sn * L_TOK + l];
            int te = edge_tokens[e * L_TOK + l];
            t_s[el][idx] = emb[tn * HID + h] + emb[te * HID + h];
        }
    }
    __syncthreads();
    float acc[16];
#pragma unroll
    for (int el = 0; el < 16; el++) acc[el] = 0.f;
    for (int k = 0; k < D_IN; k++) {
        float w = W_nbr[k * D_GNN + tid];
#pragma unroll
        for (int el = 0; el < 16; el++) acc[el] += t_s[el][k] * w;
    }
#pragma unroll
    for (int el = 0; el < 16; el++)
        atomicAdd(&g_agg[s_dst[el] * D_GNN + tid], acc[el]);
}

// ---------------- K3: fused GNN-h + transformer; writes tf32 fragment-major g_xf ----------------
__global__ __launch_bounds__(256) void k3_fused(const int* __restrict__ node_tokens,
                                                const int* __restrict__ edge_index,
                                                const float* __restrict__ emb,
                                                const float* __restrict__ W_self,
                                                const float* __restrict__ Wq, const float* __restrict__ Wk,
                                                const float* __restrict__ Wv, const float* __restrict__ Wo,
                                                const float* __restrict__ W1, const float* __restrict__ W2) {
    __shared__ float ne[8][D_IN];
    __shared__ float hn[8][D_GNN];
    __shared__ int snode[8];
    __shared__ float xsm[8][64];
    __shared__ float ksm[4][2][64];
    __shared__ float vsm[4][2][64];
    __shared__ float hsm[8][FFN_D];

    int tid = threadIdx.x, lane = tid & 31, wid = tid >> 5;
    int e_base = blockIdx.x * 4;

    if (tid < 8)
        snode[tid] = edge_index[(tid & 1) * N_EDGES + e_base + (tid >> 1)];
    __syncthreads();

    for (int idx = tid; idx < 8 * D_IN; idx += 256) {
        int j = idx >> 9, kk = idx & 511;
        int l = kk >> 6, hcol = kk & 63;
        int tok = node_tokens[snode[j] * L_TOK + l];
        ne[j][kk] = emb[tok * HID + hcol];
    }
    __syncthreads();

    {
        int c = tid & 127, grp = tid >> 7;
        float acc0 = 0.f, acc1 = 0.f, acc2 = 0.f, acc3 = 0.f;
        const float4* n0 = (const float4*)ne[grp * 4 + 0];
        const float4* n1 = (const float4*)ne[grp * 4 + 1];
        const float4* n2 = (const float4*)ne[grp * 4 + 2];
        const float4* n3 = (const float4*)ne[grp * 4 + 3];
#pragma unroll 4
        for (int k4i = 0; k4i < D_IN / 4; k4i++) {
            float4 a = n0[k4i], b = n1[k4i], cc = n2[k4i], d = n3[k4i];
            const float* wr = W_self + k4i * 4 * D_GNN + c;
            float w0 = wr[0], w1 = wr[D_GNN], w2 = wr[2 * D_GNN], w3 = wr[3 * D_GNN];
            acc0 += a.x * w0 + a.y * w1 + a.z * w2 + a.w * w3;
            acc1 += b.x * w0 + b.y * w1 + b.z * w2 + b.w * w3;
            acc2 += cc.x * w0 + cc.y * w1 + cc.z * w2 + cc.w * w3;
            acc3 += d.x * w0 + d.y * w1 + d.z * w2 + d.w * w3;
        }
        hn[grp * 4 + 0][c] = fmaxf(acc0 + g_agg[snode[grp * 4 + 0] * D_GNN + c], 0.f);
        hn[grp * 4 + 1][c] = fmaxf(acc1 + g_agg[snode[grp * 4 + 1] * D_GNN + c], 0.f);
        hn[grp * 4 + 2][c] = fmaxf(acc2 + g_agg[snode[grp * 4 + 2] * D_GNN + c], 0.f);
        hn[grp * 4 + 3][c] = fmaxf(acc3 + g_agg[snode[grp * 4 + 3] * D_GNN + c], 0.f);
    }
    __syncthreads();

    int el = wid >> 1, s = wid & 1;
    int e = e_base + el;

    const float2* hs2 = (const float2*)&hn[2 * el][s * 64];
    const float2* hd2 = (const float2*)&hn[2 * el + 1][s * 64];
    float2 xa2 = hs2[lane], xb2 = hd2[lane];
    float x0 = xa2.x + xb2.x, x1 = xa2.y + xb2.y;
    xsm[wid][2 * lane] = x0;
    xsm[wid][2 * lane + 1] = x1;
    __syncwarp();

    const float2* Wq2 = (const float2*)Wq;
    const float2* Wk2 = (const float2*)Wk;
    const float2* Wv2 = (const float2*)Wv;
    const float2* Wo2 = (const float2*)Wo;
    const float2* W22 = (const float2*)W2;

    float q0 = 0.f, q1 = 0.f, kk0 = 0.f, kk1 = 0.f, v0 = 0.f, v1 = 0.f;
    float q0b = 0.f, q1b = 0.f, kk0b = 0.f, kk1b = 0.f, v0b = 0.f, v1b = 0.f;
#pragma unroll
    for (int k = 0; k < 64; k += 2) {
        float xa = xsm[wid][k], xb = xsm[wid][k + 1];
        float2 wqa = Wq2[k * 32 + lane], wqb = Wq2[(k + 1) * 32 + lane];
        float2 wka = Wk2[k * 32 + lane], wkb = Wk2[(k + 1) * 32 + lane];
        float2 wva = Wv2[k * 32 + lane], wvb = Wv2[(k + 1) * 32 + lane];
        q0 += xa * wqa.x; q1 += xa * wqa.y;
        kk0 += xa * wka.x; kk1 += xa * wka.y;
        v0 += xa * wva.x; v1 += xa * wva.y;
        q0b += xb * wqb.x; q1b += xb * wqb.y;
        kk0b += xb * wkb.x; kk1b += xb * wkb.y;
        v0b += xb * wvb.x; v1b += xb * wvb.y;
    }
    q0 += q0b; q1 += q1b; kk0 += kk0b; kk1 += kk1b; v0 += v0b; v1 += v1b;
    ksm[el][s][2 * lane] = kk0; ksm[el][s][2 * lane + 1] = kk1;
    vsm[el][s][2 * lane] = v0;  vsm[el][s][2 * lane + 1] = v1;
    __syncthreads();

    float p0 = q0 * ksm[el][0][2 * lane] + q1 * ksm[el][0][2 * lane + 1];
    float p1 = q0 * ksm[el][1][2 * lane] + q1 * ksm[el][1][2 * lane + 1];
#pragma unroll
    for (int d = 16; d; d >>= 1) {
        p0 += __shfl_xor_sync(0xffffffffu, p0, d);
        p1 += __shfl_xor_sync(0xffffffffu, p1, d);
    }
    p0 *= 0.125f; p1 *= 0.125f;
    float m = fmaxf(p0, p1);
    float ea = __expf(p0 - m), eb = __expf(p1 - m);
    float inv = 1.f / (ea + eb);
    float a0 = ea * inv, a1 = eb * inv;

    float y0 = a0 * vsm[el][0][2 * lane]     + a1 * vsm[el][1][2 * lane];
    float y1 = a0 * vsm[el][0][2 * lane + 1] + a1 * vsm[el][1][2 * lane + 1];

    xsm[wid][2 * lane] = y0;
    xsm[wid][2 * lane + 1] = y1;
    __syncwarp();

    float o0 = 0.f, o1 = 0.f, o0b = 0.f, o1b = 0.f;
#pragma unroll
    for (int k = 0; k < 64; k += 2) {
        float ya = xsm[wid][k], yb = xsm[wid][k + 1];
        float2 woa = Wo2[k * 32 + lane], wob = Wo2[(k + 1) * 32 + lane];
        o0 += ya * woa.x; o1 += ya * woa.y;
        o0b += yb * wob.x; o1b += yb * wob.y;
    }
    x0 += o0 + o0b; x1 += o1 + o1b;

    float msum = x0 + x1;
#pragma unroll
    for (int d = 16; d; d >>= 1) msum += __shfl_xor_sync(0xffffffffu, msum, d);
    float mean = msum * (1.f / 64.f);
    float d0 = x0 - mean, d1 = x1 - mean;
    float vsum = d0 * d0 + d1 * d1;
#pragma unroll
    for (int d = 16; d; d >>= 1) vsum += __shfl_xor_sync(0xffffffffu, vsum, d);
    float rstd = rsqrtf(vsum * (1.f / 64.f) + 1e-5f);
    x0 = d0 * rstd; x1 = d1 * rstd;

    __syncwarp();
    xsm[wid][2 * lane] = x0;
    xsm[wid][2 * lane + 1] = x1;
    __syncwarp();

    float h[8];
#pragma unroll
    for (int j = 0; j < 8; j++) h[j] = 0.f;
#pragma unroll 8
    for (int k = 0; k < 64; k++) {
        float xk = xsm[wid][k];
        const float* w1r = W1 + k * FFN_D + lane;
#pragma unroll
        for (int j = 0; j < 8; j++) h[j] += xk * w1r[j * 32];
    }
#pragma unroll
    for (int j = 0; j < 8; j++) hsm[wid][j * 32 + lane] = fmaxf(h[j], 0.f);
    __syncwarp();

    float o20 = 0.f, o21 = 0.f, o20b = 0.f, o21b = 0.f;
#pragma unroll 8
    for (int f = 0; f < FFN_D; f += 2) {
        float ha = hsm[wid][f], hb = hsm[wid][f + 1];
        float2 w2a = W22[f * 32 + lane], w2b = W22[(f + 1) * 32 + lane];
        o20 += ha * w2a.x; o21 += ha * w2a.y;
        o20b += hb * w2b.x; o21b += hb * w2b.y;
    }
    float z0 = x0 + o20 + o20b, z1 = x1 + o21 + o21b;

    msum = z0 + z1;
#pragma unroll
    for (int d = 16; d; d >>= 1) msum += __shfl_xor_sync(0xffffffffu, msum, d);
    mean = msum * (1.f / 64.f);
    d0 = z0 - mean; d1 = z1 - mean;
    vsum = d0 * d0 + d1 * d1;
#pragma unroll
    for (int d = 16; d; d >>= 1) vsum += __shfl_xor_sync(0xffffffffu, vsum, d);
    rstd = rsqrtf(vsum * (1.f / 64.f) + 1e-5f);

    // ---- store tf32 fragment-major: row r = e*2+s, cols k0=2*lane, k1=2*lane+1 ----
    {
        int r = e * 2 + s;
        int rt16 = r >> 4, half = (r & 15) >> 3, gg = r & 7;
        float v0f = d0 * rstd, v1f = d1 * rstd;
        uint32_t u0, u1;
        asm("cvt.rna.tf32.f32 %0, %1;" : "=r"(u0) : "f"(v0f));
        asm("cvt.rna.tf32.f32 %0, %1;" : "=r"(u1) : "f"(v1f));
        int ka = 2 * lane, kb = 2 * lane + 1;
        int ksa = ka >> 3, k8a = ka & 7;
        int ksb = kb >> 3, k8b = kb & 7;
        g_xf[(rt16 * 8 + ksa) * 128 + half * 64 + gg * 8 + (k8a & 3) * 2 + (k8a >> 2)] = u0;
        g_xf[(rt16 * 8 + ksb) * 128 + half * 64 + gg * 8 + (k8b & 3) * 2 + (k8b >> 2)] = u1;
    }
}

// ---------------- K4: lm head, tf32 mma.sync; B-resident, A frags direct from g_xf ----------------
// Grid (250, 4): block owns 128 cols; loops 8 row-tiles of 128 with NO per-iter syncs.
#define K4_ROW_ITERS 8

__global__ __launch_bounds__(256, 2) void k4_tc(const float* __restrict__ lmW,
                                                const float* __restrict__ lmb,
                                                float* __restrict__ out) {
    __shared__ uint32_t Bs[8192];
    __shared__ float bsm[128];

    int tid = threadIdx.x;
    int cb = blockIdx.x * 128;

    // ---- B + bias fill (once per block) ----
    for (int i = tid; i < 8192; i += 256) {
        int n = i & 127, k = i >> 7;
        float v = lmW[(size_t)k * VOCAB + cb + n];
        uint32_t u; asm("cvt.rna.tf32.f32 %0, %1;" : "=r"(u) : "f"(v));
        int nt = n >> 3, gg = n & 7, ks = k >> 3, k8 = k & 7, hi = k8 >> 2, tg = k8 & 3;
        Bs[(nt * 8 + ks) * 64 + gg * 8 + tg * 2 + hi] = u;
    }
    if (tid < 128) bsm[tid] = lmb[cb + tid];
    __syncthreads();

    int lane = tid & 31, warp = tid >> 5;
    int wm = warp >> 1, wn = warp & 1;
    int g = lane >> 2, tig = lane & 3;

    // register-cached bias pairs for this warp's columns
    float2 bv[8];
#pragma unroll
    for (int nt = 0; nt < 8; nt++)
        bv[nt] = *(const float2*)&bsm[wn * 64 + nt * 8 + 2 * tig];

#pragma unroll 1
    for (int it = 0; it < K4_ROW_ITERS; it++) {
        int rb = (blockIdx.y * K4_ROW_ITERS + it) * 128;
        int rt16b = rb >> 4;

        float acc[2][8][4];
#pragma unroll
        for (int mt = 0; mt < 2; mt++)
#pragma unroll
            for (int nt = 0; nt < 8; nt++)
#pragma unroll
                for (int j = 0; j < 4; j++) acc[mt][nt][j] = 0.f;

#pragma unroll
        for (int ks = 0; ks < 8; ks++) {
            uint32_t a[2][4];
#pragma unroll
            for (int mt = 0; mt < 2; mt++) {
                const uint32_t* ap = g_xf + ((rt16b + wm * 2 + mt) * 8 + ks) * 128;
                uint2 p0 = __ldg((const uint2*)(ap + lane * 2));
                uint2 p1 = __ldg((const uint2*)(ap + 64 + lane * 2));
                a[mt][0] = p0.x; a[mt][2] = p0.y; a[mt][1] = p1.x; a[mt][3] = p1.y;
            }
#pragma unroll
            for (int nt = 0; nt < 8; nt++) {
                const uint32_t* bp = Bs + ((wn * 8 + nt) * 8 + ks) * 64;
                uint2 bb = *(const uint2*)(bp + lane * 2);
#pragma unroll
                for (int mt = 0; mt < 2; mt++) {
                    asm volatile(
                        "mma.sync.aligned.m16n8k8.row.col.f32.tf32.tf32.f32 "
                        "{%0,%1,%2,%3}, {%4,%5,%6,%7}, {%8,%9}, {%0,%1,%2,%3};\n"
                        : "+f"(acc[mt][nt][0]), "+f"(acc[mt][nt][1]),
                          "+f"(acc[mt][nt][2]), "+f"(acc[mt][nt][3])
                        : "r"(a[mt][0]), "r"(a[mt][1]), "r"(a[mt][2]), "r"(a[mt][3]),
                          "r"(bb.x), "r"(bb.y));
                }
            }
        }

        // ---- epilogue: exp + store (unnormalized) + rowsum atomics ----
#pragma unroll
        for (int mt = 0; mt < 2; mt++) {
            int r_lo = rb + wm * 32 + mt * 16 + g;
            float* plo = out + (size_t)LBL_OFF + (size_t)r_lo * VOCAB + cb + wn * 64 + 2 * tig;
            float* phi = plo + (size_t)8 * VOCAB;
            float slo = 0.f, shi = 0.f;
#pragma unroll
            for (int nt = 0; nt < 8; nt++) {
                float e0 = __expf(acc[mt][nt][0] + bv[nt].x);
                float e1 = __expf(acc[mt][nt][1] + bv[nt].y);
                float e2 = __expf(acc[mt][nt][2] + bv[nt].x);
                float e3 = __expf(acc[mt][nt][3] + bv[nt].y);
                slo += e0 + e1;
                shi += e2 + e3;
                *(float2*)(plo + nt * 8) = make_float2(e0, e1);
                *(float2*)(phi + nt * 8) = make_float2(e2, e3);
            }
            slo += __shfl_xor_sync(0xffffffffu, slo, 1);
            slo += __shfl_xor_sync(0xffffffffu, slo, 2);
            shi += __shfl_xor_sync(0xffffffffu, shi, 1);
            shi += __shfl_xor_sync(0xffffffffu, shi, 2);
            if (tig == 0) {
                atomicAdd(&g_rowsum[r_lo], slo);
                atomicAdd(&g_rowsum[r_lo + 8], shi);
            }
        }
    }
}

// ---------------- K5: in-place normalization (float4 RMW) ----------------
__global__ __launch_bounds__(512) void k5_norm(float* __restrict__ out) {
    int row = blockIdx.x;
    float inv = 1.f / g_rowsum[row];
    float4* p = (float4*)(out + (size_t)LBL_OFF + (size_t)row * VOCAB);
#pragma unroll 4
    for (int i = threadIdx.x; i < VOCAB / 4; i += 512) {
        float4 v = p[i];
        v.x *= inv; v.y *= inv; v.z *= inv; v.w *= inv;
        p[i] = v;
    }
}

// ---------------- K6: labels ----------------
__global__ void k6_labels(const int* __restrict__ edge_tokens, float* __restrict__ out) {
    int idx = blockIdx.x * 256 + threadIdx.x;
    if (idx < N_EDGES * L_TOK) {
        int e = idx >> 3;
        int tok = edge_tokens[idx];
        int lab = (e == 0 && tok >= 4) ? tok : -100;
        out[idx] = (float)lab;
    }
}

// ---------------- launch ----------------
extern "C" void kernel_launch(void* const* d_in, const int* in_sizes, int n_in,
                              void* d_out, int out_size) {
    const int*   node_tokens = (const int*)d_in[0];
    const int*   edge_tokens = (const int*)d_in[1];
    const int*   edge_index  = (const int*)d_in[2];
    const float* emb    = (const float*)d_in[3];
    const float* W_self = (const float*)d_in[4];
    const float* W_nbr  = (const float*)d_in[5];
    const float* Wq     = (const float*)d_in[6];
    const float* Wk     = (const float*)d_in[7];
    const float* Wv     = (const float*)d_in[8];
    const float* Wo     = (const float*)d_in[9];
    const float* W1     = (const float*)d_in[10];
    const float* W2     = (const float*)d_in[11];
    const float* lmW    = (const float*)d_in[12];
    const float* lmb    = (const float*)d_in[13];
    float* out = (float*)d_out;

    k0_zero<<<2080, 128>>>(edge_index);
    k1_msg<<<128, 128>>>(node_tokens, edge_tokens, edge_index, emb, W_nbr);
    k3_fused<<<512, 256>>>(node_tokens, edge_index, emb, W_self,
                           Wq, Wk, Wv, Wo, W1, W2);
    k4_tc<<<dim3(250, 4), 256>>>(lmW, lmb, out);
    k5_norm<<<4096, 512>>>(out);
    k6_labels<<<64, 256>>>(edge_tokens, out);
}

// round 9
// speedup vs baseline: 1.4214x; 1.0516x over previous
#include <cuda_runtime.h>
#include <cstdint>

#define N_NODES 100000
#define N_EDGES 2048
#define L_TOK 8
#define HID 64
#define D_IN 512      // L_TOK * HID
#define D_GNN 128
#define VOCAB 32000
#define FFN_D 256
#define NROWS (N_EDGES * 2)   // 4096 lm-head rows
#define LBL_OFF 16384         // labels occupy [0, 16384)

// ---------------- device scratch (no allocations allowed) ----------------
__device__ float g_agg[N_NODES * D_GNN];          // only dst rows ever touched
__device__ uint32_t g_xf[256 * 8 * 128];          // x in tf32 fragment-major
__device__ float g_rowsum[NROWS];

// ---------------- K0: zero touched agg rows + row sums ----------------
__global__ void k0_zero(const int* __restrict__ edge_index) {
    int b = blockIdx.x, t = threadIdx.x;
    if (b < N_EDGES) {
        int dst = edge_index[N_EDGES + b];
        g_agg[dst * D_GNN + t] = 0.f;
    } else {
        int i = (b - N_EDGES) * 128 + t;
        if (i < NROWS) g_rowsum[i] = 0.f;
    }
}

// ---------------- K1: msg = (node_emb[src] + edge_emb) @ W_nbr; scatter-add at dst ----------------
__global__ void k1_msg(const int* __restrict__ node_tokens,
                       const int* __restrict__ edge_tokens,
                       const int* __restrict__ edge_index,
                       const float* __restrict__ emb,
                       const float* __restrict__ W_nbr) {
    __shared__ float t_s[16][D_IN];
    __shared__ int s_src[16], s_dst[16];
    int b = blockIdx.x, tid = threadIdx.x;
    int e0 = b * 16;
    if (tid < 16) {
        s_src[tid] = edge_index[e0 + tid];
        s_dst[tid] = edge_index[N_EDGES + e0 + tid];
    }
    __syncthreads();
    for (int el = 0; el < 16; el++) {
        int e = e0 + el;
        int sn = s_src[el];
        for (int idx = tid; idx < D_IN; idx += 128) {
            int l = idx >> 6, h = idx & 63;
            int tn = node_tokens[sn * L_TOK + l];
            int te = edge_tokens[e * L_TOK + l];
            t_s[el][idx] = emb[tn * HID + h] + emb[te * HID + h];
        }
    }
    __syncthreads();
    float acc[16];
#pragma unroll
    for (int el = 0; el < 16; el++) acc[el] = 0.f;
    for (int k = 0; k < D_IN; k++) {
        float w = W_nbr[k * D_GNN + tid];
#pragma unroll
        for (int el = 0; el < 16; el++) acc[el] += t_s[el][k] * w;
    }
#pragma unroll
    for (int el = 0; el < 16; el++)
        atomicAdd(&g_agg[s_dst[el] * D_GNN + tid], acc[el]);
}

// ---------------- K3: fused GNN-h + transformer; writes tf32 fragment-major g_xf ----------------
__global__ __launch_bounds__(256) void k3_fused(const int* __restrict__ node_tokens,
                                                const int* __restrict__ edge_index,
                                                const float* __restrict__ emb,
                                                const float* __restrict__ W_self,
                                                const float* __restrict__ Wq, const float* __restrict__ Wk,
                                                const float* __restrict__ Wv, const float* __restrict__ Wo,
                                                const float* __restrict__ W1, const float* __restrict__ W2) {
    __shared__ float ne[8][D_IN];
    __shared__ float hn[8][D_GNN];
    __shared__ int snode[8];
    __shared__ float xsm[8][64];
    __shared__ float ksm[4][2][64];
    __shared__ float vsm[4][2][64];
    __shared__ float hsm[8][FFN_D];

    int tid = threadIdx.x, lane = tid & 31, wid = tid >> 5;
    int e_base = blockIdx.x * 4;

    if (tid < 8)
        snode[tid] = edge_index[(tid & 1) * N_EDGES + e_base + (tid >> 1)];
    __syncthreads();

    for (int idx = tid; idx < 8 * D_IN; idx += 256) {
        int j = idx >> 9, kk = idx & 511;
        int l = kk >> 6, hcol = kk & 63;
        int tok = node_tokens[snode[j] * L_TOK + l];
        ne[j][kk] = emb[tok * HID + hcol];
    }
    __syncthreads();

    {
        int c = tid & 127, grp = tid >> 7;
        float acc0 = 0.f, acc1 = 0.f, acc2 = 0.f, acc3 = 0.f;
        const float4* n0 = (const float4*)ne[grp * 4 + 0];
        const float4* n1 = (const float4*)ne[grp * 4 + 1];
        const float4* n2 = (const float4*)ne[grp * 4 + 2];
        const float4* n3 = (const float4*)ne[grp * 4 + 3];
#pragma unroll 4
        for (int k4i = 0; k4i < D_IN / 4; k4i++) {
            float4 a = n0[k4i], b = n1[k4i], cc = n2[k4i], d = n3[k4i];
            const float* wr = W_self + k4i * 4 * D_GNN + c;
            float w0 = wr[0], w1 = wr[D_GNN], w2 = wr[2 * D_GNN], w3 = wr[3 * D_GNN];
            acc0 += a.x * w0 + a.y * w1 + a.z * w2 + a.w * w3;
            acc1 += b.x * w0 + b.y * w1 + b.z * w2 + b.w * w3;
            acc2 += cc.x * w0 + cc.y * w1 + cc.z * w2 + cc.w * w3;
            acc3 += d.x * w0 + d.y * w1 + d.z * w2 + d.w * w3;
        }
        hn[grp * 4 + 0][c] = fmaxf(acc0 + g_agg[snode[grp * 4 + 0] * D_GNN + c], 0.f);
        hn[grp * 4 + 1][c] = fmaxf(acc1 + g_agg[snode[grp * 4 + 1] * D_GNN + c], 0.f);
        hn[grp * 4 + 2][c] = fmaxf(acc2 + g_agg[snode[grp * 4 + 2] * D_GNN + c], 0.f);
        hn[grp * 4 + 3][c] = fmaxf(acc3 + g_agg[snode[grp * 4 + 3] * D_GNN + c], 0.f);
    }
    __syncthreads();

    int el = wid >> 1, s = wid & 1;
    int e = e_base + el;

    const float2* hs2 = (const float2*)&hn[2 * el][s * 64];
    const float2* hd2 = (const float2*)&hn[2 * el + 1][s * 64];
    float2 xa2 = hs2[lane], xb2 = hd2[lane];
    float x0 = xa2.x + xb2.x, x1 = xa2.y + xb2.y;
    xsm[wid][2 * lane] = x0;
    xsm[wid][2 * lane + 1] = x1;
    __syncwarp();

    const float2* Wq2 = (const float2*)Wq;
    const float2* Wk2 = (const float2*)Wk;
    const float2* Wv2 = (const float2*)Wv;
    const float2* Wo2 = (const float2*)Wo;
    const float2* W22 = (const float2*)W2;

    float q0 = 0.f, q1 = 0.f, kk0 = 0.f, kk1 = 0.f, v0 = 0.f, v1 = 0.f;
    float q0b = 0.f, q1b = 0.f, kk0b = 0.f, kk1b = 0.f, v0b = 0.f, v1b = 0.f;
#pragma unroll
    for (int k = 0; k < 64; k += 2) {
        float xa = xsm[wid][k], xb = xsm[wid][k + 1];
        float2 wqa = Wq2[k * 32 + lane], wqb = Wq2[(k + 1) * 32 + lane];
        float2 wka = Wk2[k * 32 + lane], wkb = Wk2[(k + 1) * 32 + lane];
        float2 wva = Wv2[k * 32 + lane], wvb = Wv2[(k + 1) * 32 + lane];
        q0 += xa * wqa.x; q1 += xa * wqa.y;
        kk0 += xa * wka.x; kk1 += xa * wka.y;
        v0 += xa * wva.x; v1 += xa * wva.y;
        q0b += xb * wqb.x; q1b += xb * wqb.y;
        kk0b += xb * wkb.x; kk1b += xb * wkb.y;
        v0b += xb * wvb.x; v1b += xb * wvb.y;
    }
    q0 += q0b; q1 += q1b; kk0 += kk0b; kk1 += kk1b; v0 += v0b; v1 += v1b;
    ksm[el][s][2 * lane] = kk0; ksm[el][s][2 * lane + 1] = kk1;
    vsm[el][s][2 * lane] = v0;  vsm[el][s][2 * lane + 1] = v1;
    __syncthreads();

    float p0 = q0 * ksm[el][0][2 * lane] + q1 * ksm[el][0][2 * lane + 1];
    float p1 = q0 * ksm[el][1][2 * lane] + q1 * ksm[el][1][2 * lane + 1];
#pragma unroll
    for (int d = 16; d; d >>= 1) {
        p0 += __shfl_xor_sync(0xffffffffu, p0, d);
        p1 += __shfl_xor_sync(0xffffffffu, p1, d);
    }
    p0 *= 0.125f; p1 *= 0.125f;
    float m = fmaxf(p0, p1);
    float ea = __expf(p0 - m), eb = __expf(p1 - m);
    float inv = 1.f / (ea + eb);
    float a0 = ea * inv, a1 = eb * inv;

    float y0 = a0 * vsm[el][0][2 * lane]     + a1 * vsm[el][1][2 * lane];
    float y1 = a0 * vsm[el][0][2 * lane + 1] + a1 * vsm[el][1][2 * lane + 1];

    xsm[wid][2 * lane] = y0;
    xsm[wid][2 * lane + 1] = y1;
    __syncwarp();

    float o0 = 0.f, o1 = 0.f, o0b = 0.f, o1b = 0.f;
#pragma unroll
    for (int k = 0; k < 64; k += 2) {
        float ya = xsm[wid][k], yb = xsm[wid][k + 1];
        float2 woa = Wo2[k * 32 + lane], wob = Wo2[(k + 1) * 32 + lane];
        o0 += ya * woa.x; o1 += ya * woa.y;
        o0b += yb * wob.x; o1b += yb * wob.y;
    }
    x0 += o0 + o0b; x1 += o1 + o1b;

    float msum = x0 + x1;
#pragma unroll
    for (int d = 16; d; d >>= 1) msum += __shfl_xor_sync(0xffffffffu, msum, d);
    float mean = msum * (1.f / 64.f);
    float d0 = x0 - mean, d1 = x1 - mean;
    float vsum = d0 * d0 + d1 * d1;
#pragma unroll
    for (int d = 16; d; d >>= 1) vsum += __shfl_xor_sync(0xffffffffu, vsum, d);
    float rstd = rsqrtf(vsum * (1.f / 64.f) + 1e-5f);
    x0 = d0 * rstd; x1 = d1 * rstd;

    __syncwarp();
    xsm[wid][2 * lane] = x0;
    xsm[wid][2 * lane + 1] = x1;
    __syncwarp();

    float h[8];
#pragma unroll
    for (int j = 0; j < 8; j++) h[j] = 0.f;
#pragma unroll 8
    for (int k = 0; k < 64; k++) {
        float xk = xsm[wid][k];
        const float* w1r = W1 + k * FFN_D + lane;
#pragma unroll
        for (int j = 0; j < 8; j++) h[j] += xk * w1r[j * 32];
    }
#pragma unroll
    for (int j = 0; j < 8; j++) hsm[wid][j * 32 + lane] = fmaxf(h[j], 0.f);
    __syncwarp();

    float o20 = 0.f, o21 = 0.f, o20b = 0.f, o21b = 0.f;
#pragma unroll 8
    for (int f = 0; f < FFN_D; f += 2) {
        float ha = hsm[wid][f], hb = hsm[wid][f + 1];
        float2 w2a = W22[f * 32 + lane], w2b = W22[(f + 1) * 32 + lane];
        o20 += ha * w2a.x; o21 += ha * w2a.y;
        o20b += hb * w2b.x; o21b += hb * w2b.y;
    }
    float z0 = x0 + o20 + o20b, z1 = x1 + o21 + o21b;

    msum = z0 + z1;
#pragma unroll
    for (int d = 16; d; d >>= 1) msum += __shfl_xor_sync(0xffffffffu, msum, d);
    mean = msum * (1.f / 64.f);
    d0 = z0 - mean; d1 = z1 - mean;
    vsum = d0 * d0 + d1 * d1;
#pragma unroll
    for (int d = 16; d; d >>= 1) vsum += __shfl_xor_sync(0xffffffffu, vsum, d);
    rstd = rsqrtf(vsum * (1.f / 64.f) + 1e-5f);

    {
        int r = e * 2 + s;
        int rt16 = r >> 4, half = (r & 15) >> 3, gg = r & 7;
        float v0f = d0 * rstd, v1f = d1 * rstd;
        uint32_t u0, u1;
        asm("cvt.rna.tf32.f32 %0, %1;" : "=r"(u0) : "f"(v0f));
        asm("cvt.rna.tf32.f32 %0, %1;" : "=r"(u1) : "f"(v1f));
        int ka = 2 * lane, kb = 2 * lane + 1;
        int ksa = ka >> 3, k8a = ka & 7;
        int ksb = kb >> 3, k8b = kb & 7;
        g_xf[(rt16 * 8 + ksa) * 128 + half * 64 + gg * 8 + (k8a & 3) * 2 + (k8a >> 2)] = u0;
        g_xf[(rt16 * 8 + ksb) * 128 + half * 64 + gg * 8 + (k8b & 3) * 2 + (k8b >> 2)] = u1;
    }
}

// ---------------- K4: lm head, tf32 mma.sync; B-resident, A frags from g_xf; two-pass ----------------
// Pass A (STORE=false): GEMM + exp + rowsum atomics (no probs store).
// Pass B (STORE=true):  GEMM + exp * (1/rowsum) + store.
#define K4_ROW_ITERS 8

template <bool STORE>
__global__ __launch_bounds__(256, 2) void k4_tc(const float* __restrict__ lmW,
                                                const float* __restrict__ lmb,
                                                float* __restrict__ out) {
    __shared__ uint32_t Bs[8192];
    __shared__ float bsm[128];

    int tid = threadIdx.x;
    int cb = blockIdx.x * 128;

    for (int i = tid; i < 8192; i += 256) {
        int n = i & 127, k = i >> 7;
        float v = lmW[(size_t)k * VOCAB + cb + n];
        uint32_t u; asm("cvt.rna.tf32.f32 %0, %1;" : "=r"(u) : "f"(v));
        int nt = n >> 3, gg = n & 7, ks = k >> 3, k8 = k & 7, hi = k8 >> 2, tg = k8 & 3;
        Bs[(nt * 8 + ks) * 64 + gg * 8 + tg * 2 + hi] = u;
    }
    if (tid < 128) bsm[tid] = lmb[cb + tid];
    __syncthreads();

    int lane = tid & 31, warp = tid >> 5;
    int wm = warp >> 1, wn = warp & 1;
    int g = lane >> 2, tig = lane & 3;

    float2 bv[8];
#pragma unroll
    for (int nt = 0; nt < 8; nt++)
        bv[nt] = *(const float2*)&bsm[wn * 64 + nt * 8 + 2 * tig];

#pragma unroll 1
    for (int it = 0; it < K4_ROW_ITERS; it++) {
        int rb = (blockIdx.y * K4_ROW_ITERS + it) * 128;
        int rt16b = rb >> 4;

        float acc[2][8][4];
#pragma unroll
        for (int mt = 0; mt < 2; mt++)
#pragma unroll
            for (int nt = 0; nt < 8; nt++)
#pragma unroll
                for (int j = 0; j < 4; j++) acc[mt][nt][j] = 0.f;

#pragma unroll
        for (int ks = 0; ks < 8; ks++) {
            uint32_t a[2][4];
#pragma unroll
            for (int mt = 0; mt < 2; mt++) {
                const uint32_t* ap = g_xf + ((rt16b + wm * 2 + mt) * 8 + ks) * 128;
                uint2 p0 = __ldg((const uint2*)(ap + lane * 2));
                uint2 p1 = __ldg((const uint2*)(ap + 64 + lane * 2));
                a[mt][0] = p0.x; a[mt][2] = p0.y; a[mt][1] = p1.x; a[mt][3] = p1.y;
            }
#pragma unroll
            for (int nt = 0; nt < 8; nt++) {
                const uint32_t* bp = Bs + ((wn * 8 + nt) * 8 + ks) * 64;
                uint2 bb = *(const uint2*)(bp + lane * 2);
#pragma unroll
                for (int mt = 0; mt < 2; mt++) {
                    asm volatile(
                        "mma.sync.aligned.m16n8k8.row.col.f32.tf32.tf32.f32 "
                        "{%0,%1,%2,%3}, {%4,%5,%6,%7}, {%8,%9}, {%0,%1,%2,%3};\n"
                        : "+f"(acc[mt][nt][0]), "+f"(acc[mt][nt][1]),
                          "+f"(acc[mt][nt][2]), "+f"(acc[mt][nt][3])
                        : "r"(a[mt][0]), "r"(a[mt][1]), "r"(a[mt][2]), "r"(a[mt][3]),
                          "r"(bb.x), "r"(bb.y));
                }
            }
        }

#pragma unroll
        for (int mt = 0; mt < 2; mt++) {
            int r_lo = rb + wm * 32 + mt * 16 + g;
            if (STORE) {
                float inv_lo = 1.f / g_rowsum[r_lo];
                float inv_hi = 1.f / g_rowsum[r_lo + 8];
                float* plo = out + (size_t)LBL_OFF + (size_t)r_lo * VOCAB + cb + wn * 64 + 2 * tig;
                float* phi = plo + (size_t)8 * VOCAB;
#pragma unroll
                for (int nt = 0; nt < 8; nt++) {
                    float e0 = __expf(acc[mt][nt][0] + bv[nt].x) * inv_lo;
                    float e1 = __expf(acc[mt][nt][1] + bv[nt].y) * inv_lo;
                    float e2 = __expf(acc[mt][nt][2] + bv[nt].x) * inv_hi;
                    float e3 = __expf(acc[mt][nt][3] + bv[nt].y) * inv_hi;
                    *(float2*)(plo + nt * 8) = make_float2(e0, e1);
                    *(float2*)(phi + nt * 8) = make_float2(e2, e3);
                }
            } else {
                float slo = 0.f, shi = 0.f;
#pragma unroll
                for (int nt = 0; nt < 8; nt++) {
                    slo += __expf(acc[mt][nt][0] + bv[nt].x) + __expf(acc[mt][nt][1] + bv[nt].y);
                    shi += __expf(acc[mt][nt][2] + bv[nt].x) + __expf(acc[mt][nt][3] + bv[nt].y);
                }
                slo += __shfl_xor_sync(0xffffffffu, slo, 1);
                slo += __shfl_xor_sync(0xffffffffu, slo, 2);
                shi += __shfl_xor_sync(0xffffffffu, shi, 1);
                shi += __shfl_xor_sync(0xffffffffu, shi, 2);
                if (tig == 0) {
                    atomicAdd(&g_rowsum[r_lo], slo);
                    atomicAdd(&g_rowsum[r_lo + 8], shi);
                }
            }
        }
    }
}

// ---------------- K6: labels ----------------
__global__ void k6_labels(const int* __restrict__ edge_tokens, float* __restrict__ out) {
    int idx = blockIdx.x * 256 + threadIdx.x;
    if (idx < N_EDGES * L_TOK) {
        int e = idx >> 3;
        int tok = edge_tokens[idx];
        int lab = (e == 0 && tok >= 4) ? tok : -100;
        out[idx] = (float)lab;
    }
}

// ---------------- launch ----------------
extern "C" void kernel_launch(void* const* d_in, const int* in_sizes, int n_in,
                              void* d_out, int out_size) {
    const int*   node_tokens = (const int*)d_in[0];
    const int*   edge_tokens = (const int*)d_in[1];
    const int*   edge_index  = (const int*)d_in[2];
    const float* emb    = (const float*)d_in[3];
    const float* W_self = (const float*)d_in[4];
    const float* W_nbr  = (const float*)d_in[5];
    const float* Wq     = (const float*)d_in[6];
    const float* Wk     = (const float*)d_in[7];
    const float* Wv     = (const float*)d_in[8];
    const float* Wo     = (const float*)d_in[9];
    const float* W1     = (const float*)d_in[10];
    const float* W2     = (const float*)d_in[11];
    const float* lmW    = (const float*)d_in[12];
    const float* lmb    = (const float*)d_in[13];
    float* out = (float*)d_out;

    k0_zero<<<2080, 128>>>(edge_index);
    k1_msg<<<128, 128>>>(node_tokens, edge_tokens, edge_index, emb, W_nbr);
    k3_fused<<<512, 256>>>(node_tokens, edge_index, emb, W_self,
                           Wq, Wk, Wv, Wo, W1, W2);
    k4_tc<false><<<dim3(250, 4), 256>>>(lmW, lmb, out);
    k4_tc<true><<<dim3(250, 4), 256>>>(lmW, lmb, out);
    k6_labels<<<64, 256>>>(edge_tokens, out);
}

// round 10
// speedup vs baseline: 1.5940x; 1.1214x over previous
#include <cuda_runtime.h>
#include <cuda_bf16.h>
#include <cstdint>

#define N_NODES 100000
#define N_EDGES 2048
#define L_TOK 8
#define HID 64
#define D_IN 512      // L_TOK * HID
#define D_GNN 128
#define VOCAB 32000
#define FFN_D 256
#define NROWS (N_EDGES * 2)   // 4096 lm-head rows
#define LBL_OFF 16384         // labels occupy [0, 16384)

// ---------------- device scratch (no allocations allowed) ----------------
__device__ float g_agg[N_NODES * D_GNN];          // only dst rows ever touched
__device__ uint32_t g_xf[256 * 4 * 128];          // x in bf16x2 fragment-major: [rt16][ks4][word]
__device__ float g_rowsum[NROWS];

__device__ __forceinline__ uint32_t pack_bf16x2(float lo, float hi) {
    __nv_bfloat162 b = __float22bfloat162_rn(make_float2(lo, hi));
    return *(uint32_t*)&b;
}

// ---------------- K0: zero touched agg rows + row sums ----------------
__global__ void k0_zero(const int* __restrict__ edge_index) {
    int b = blockIdx.x, t = threadIdx.x;
    if (b < N_EDGES) {
        int dst = edge_index[N_EDGES + b];
        g_agg[dst * D_GNN + t] = 0.f;
    } else {
        int i = (b - N_EDGES) * 128 + t;
        if (i < NROWS) g_rowsum[i] = 0.f;
    }
}

// ---------------- K1: msg = (node_emb[src] + edge_emb) @ W_nbr; scatter-add at dst ----------------
__global__ void k1_msg(const int* __restrict__ node_tokens,
                       const int* __restrict__ edge_tokens,
                       const int* __restrict__ edge_index,
                       const float* __restrict__ emb,
                       const float* __restrict__ W_nbr) {
    __shared__ float t_s[16][D_IN];
    __shared__ int s_src[16], s_dst[16];
    int b = blockIdx.x, tid = threadIdx.x;
    int e0 = b * 16;
    if (tid < 16) {
        s_src[tid] = edge_index[e0 + tid];
        s_dst[tid] = edge_index[N_EDGES + e0 + tid];
    }
    __syncthreads();
    for (int el = 0; el < 16; el++) {
        int e = e0 + el;
        int sn = s_src[el];
        for (int idx = tid; idx < D_IN; idx += 128) {
            int l = idx >> 6, h = idx & 63;
            int tn = node_tokens[sn * L_TOK + l];
            int te = edge_tokens[e * L_TOK + l];
            t_s[el][idx] = emb[tn * HID + h] + emb[te * HID + h];
        }
    }
    __syncthreads();
    float acc[16];
#pragma unroll
    for (int el = 0; el < 16; el++) acc[el] = 0.f;
    for (int k = 0; k < D_IN; k++) {
        float w = W_nbr[k * D_GNN + tid];
#pragma unroll
        for (int el = 0; el < 16; el++) acc[el] += t_s[el][k] * w;
    }
#pragma unroll
    for (int el = 0; el < 16; el++)
        atomicAdd(&g_agg[s_dst[el] * D_GNN + tid], acc[el]);
}

// ---------------- K3: fused GNN-h + transformer; writes bf16 fragment-major g_xf ----------------
__global__ __launch_bounds__(256) void k3_fused(const int* __restrict__ node_tokens,
                                                const int* __restrict__ edge_index,
                                                const float* __restrict__ emb,
                                                const float* __restrict__ W_self,
                                                const float* __restrict__ Wq, const float* __restrict__ Wk,
                                                const float* __restrict__ Wv, const float* __restrict__ Wo,
                                                const float* __restrict__ W1, const float* __restrict__ W2) {
    __shared__ float ne[8][D_IN];
    __shared__ float hn[8][D_GNN];
    __shared__ int snode[8];
    __shared__ float xsm[8][64];
    __shared__ float ksm[4][2][64];
    __shared__ float vsm[4][2][64];
    __shared__ float hsm[8][FFN_D];

    int tid = threadIdx.x, lane = tid & 31, wid = tid >> 5;
    int e_base = blockIdx.x * 4;

    if (tid < 8)
        snode[tid] = edge_index[(tid & 1) * N_EDGES + e_base + (tid >> 1)];
    __syncthreads();

    for (int idx = tid; idx < 8 * D_IN; idx += 256) {
        int j = idx >> 9, kk = idx & 511;
        int l = kk >> 6, hcol = kk & 63;
        int tok = node_tokens[snode[j] * L_TOK + l];
        ne[j][kk] = emb[tok * HID + hcol];
    }
    __syncthreads();

    {
        int c = tid & 127, grp = tid >> 7;
        float acc0 = 0.f, acc1 = 0.f, acc2 = 0.f, acc3 = 0.f;
        const float4* n0 = (const float4*)ne[grp * 4 + 0];
        const float4* n1 = (const float4*)ne[grp * 4 + 1];
        const float4* n2 = (const float4*)ne[grp * 4 + 2];
        const float4* n3 = (const float4*)ne[grp * 4 + 3];
#pragma unroll 4
        for (int k4i = 0; k4i < D_IN / 4; k4i++) {
            float4 a = n0[k4i], b = n1[k4i], cc = n2[k4i], d = n3[k4i];
            const float* wr = W_self + k4i * 4 * D_GNN + c;
            float w0 = wr[0], w1 = wr[D_GNN], w2 = wr[2 * D_GNN], w3 = wr[3 * D_GNN];
            acc0 += a.x * w0 + a.y * w1 + a.z * w2 + a.w * w3;
            acc1 += b.x * w0 + b.y * w1 + b.z * w2 + b.w * w3;
            acc2 += cc.x * w0 + cc.y * w1 + cc.z * w2 + cc.w * w3;
            acc3 += d.x * w0 + d.y * w1 + d.z * w2 + d.w * w3;
        }
        hn[grp * 4 + 0][c] = fmaxf(acc0 + g_agg[snode[grp * 4 + 0] * D_GNN + c], 0.f);
        hn[grp * 4 + 1][c] = fmaxf(acc1 + g_agg[snode[grp * 4 + 1] * D_GNN + c], 0.f);
        hn[grp * 4 + 2][c] = fmaxf(acc2 + g_agg[snode[grp * 4 + 2] * D_GNN + c], 0.f);
        hn[grp * 4 + 3][c] = fmaxf(acc3 + g_agg[snode[grp * 4 + 3] * D_GNN + c], 0.f);
    }
    __syncthreads();

    int el = wid >> 1, s = wid & 1;
    int e = e_base + el;

    const float2* hs2 = (const float2*)&hn[2 * el][s * 64];
    const float2* hd2 = (const float2*)&hn[2 * el + 1][s * 64];
    float2 xa2 = hs2[lane], xb2 = hd2[lane];
    float x0 = xa2.x + xb2.x, x1 = xa2.y + xb2.y;
    xsm[wid][2 * lane] = x0;
    xsm[wid][2 * lane + 1] = x1;
    __syncwarp();

    const float2* Wq2 = (const float2*)Wq;
    const float2* Wk2 = (const float2*)Wk;
    const float2* Wv2 = (const float2*)Wv;
    const float2* Wo2 = (const float2*)Wo;
    const float2* W22 = (const float2*)W2;

    float q0 = 0.f, q1 = 0.f, kk0 = 0.f, kk1 = 0.f, v0 = 0.f, v1 = 0.f;
    float q0b = 0.f, q1b = 0.f, kk0b = 0.f, kk1b = 0.f, v0b = 0.f, v1b = 0.f;
#pragma unroll
    for (int k = 0; k < 64; k += 2) {
        float xa = xsm[wid][k], xb = xsm[wid][k + 1];
        float2 wqa = Wq2[k * 32 + lane], wqb = Wq2[(k + 1) * 32 + lane];
        float2 wka = Wk2[k * 32 + lane], wkb = Wk2[(k + 1) * 32 + lane];
        float2 wva = Wv2[k * 32 + lane], wvb = Wv2[(k + 1) * 32 + lane];
        q0 += xa * wqa.x; q1 += xa * wqa.y;
        kk0 += xa * wka.x; kk1 += xa * wka.y;
        v0 += xa * wva.x; v1 += xa * wva.y;
        q0b += xb * wqb.x; q1b += xb * wqb.y;
        kk0b += xb * wkb.x; kk1b += xb * wkb.y;
        v0b += xb * wvb.x; v1b += xb * wvb.y;
    }
    q0 += q0b; q1 += q1b; kk0 += kk0b; kk1 += kk1b; v0 += v0b; v1 += v1b;
    ksm[el][s][2 * lane] = kk0; ksm[el][s][2 * lane + 1] = kk1;
    vsm[el][s][2 * lane] = v0;  vsm[el][s][2 * lane + 1] = v1;
    __syncthreads();

    float p0 = q0 * ksm[el][0][2 * lane] + q1 * ksm[el][0][2 * lane + 1];
    float p1 = q0 * ksm[el][1][2 * lane] + q1 * ksm[el][1][2 * lane + 1];
#pragma unroll
    for (int d = 16; d; d >>= 1) {
        p0 += __shfl_xor_sync(0xffffffffu, p0, d);
        p1 += __shfl_xor_sync(0xffffffffu, p1, d);
    }
    p0 *= 0.125f; p1 *= 0.125f;
    float m = fmaxf(p0, p1);
    float ea = __expf(p0 - m), eb = __expf(p1 - m);
    float inv = 1.f / (ea + eb);
    float a0 = ea * inv, a1 = eb * inv;

    float y0 = a0 * vsm[el][0][2 * lane]     + a1 * vsm[el][1][2 * lane];
    float y1 = a0 * vsm[el][0][2 * lane + 1] + a1 * vsm[el][1][2 * lane + 1];

    xsm[wid][2 * lane] = y0;
    xsm[wid][2 * lane + 1] = y1;
    __syncwarp();

    float o0 = 0.f, o1 = 0.f, o0b = 0.f, o1b = 0.f;
#pragma unroll
    for (int k = 0; k < 64; k += 2) {
        float ya = xsm[wid][k], yb = xsm[wid][k + 1];
        float2 woa = Wo2[k * 32 + lane], wob = Wo2[(k + 1) * 32 + lane];
        o0 += ya * woa.x; o1 += ya * woa.y;
        o0b += yb * wob.x; o1b += yb * wob.y;
    }
    x0 += o0 + o0b; x1 += o1 + o1b;

    float msum = x0 + x1;
#pragma unroll
    for (int d = 16; d; d >>= 1) msum += __shfl_xor_sync(0xffffffffu, msum, d);
    float mean = msum * (1.f / 64.f);
    float d0 = x0 - mean, d1 = x1 - mean;
    float vsum = d0 * d0 + d1 * d1;
#pragma unroll
    for (int d = 16; d; d >>= 1) vsum += __shfl_xor_sync(0xffffffffu, vsum, d);
    float rstd = rsqrtf(vsum * (1.f / 64.f) + 1e-5f);
    x0 = d0 * rstd; x1 = d1 * rstd;

    __syncwarp();
    xsm[wid][2 * lane] = x0;
    xsm[wid][2 * lane + 1] = x1;
    __syncwarp();

    float h[8];
#pragma unroll
    for (int j = 0; j < 8; j++) h[j] = 0.f;
#pragma unroll 8
    for (int k = 0; k < 64; k++) {
        float xk = xsm[wid][k];
        const float* w1r = W1 + k * FFN_D + lane;
#pragma unroll
        for (int j = 0; j < 8; j++) h[j] += xk * w1r[j * 32];
    }
#pragma unroll
    for (int j = 0; j < 8; j++) hsm[wid][j * 32 + lane] = fmaxf(h[j], 0.f);
    __syncwarp();

    float o20 = 0.f, o21 = 0.f, o20b = 0.f, o21b = 0.f;
#pragma unroll 8
    for (int f = 0; f < FFN_D; f += 2) {
        float ha = hsm[wid][f], hb = hsm[wid][f + 1];
        float2 w2a = W22[f * 32 + lane], w2b = W22[(f + 1) * 32 + lane];
        o20 += ha * w2a.x; o21 += ha * w2a.y;
        o20b += hb * w2b.x; o21b += hb * w2b.y;
    }
    float z0 = x0 + o20 + o20b, z1 = x1 + o21 + o21b;

    msum = z0 + z1;
#pragma unroll
    for (int d = 16; d; d >>= 1) msum += __shfl_xor_sync(0xffffffffu, msum, d);
    mean = msum * (1.f / 64.f);
    d0 = z0 - mean; d1 = z1 - mean;
    vsum = d0 * d0 + d1 * d1;
#pragma unroll
    for (int d = 16; d; d >>= 1) vsum += __shfl_xor_sync(0xffffffffu, vsum, d);
    rstd = rsqrtf(vsum * (1.f / 64.f) + 1e-5f);

    // ---- store bf16x2 fragment-major: row r = e*2+s, lane owns kpair w=lane ----
    {
        int r = e * 2 + s;
        int rt16 = r >> 4, half = (r & 15) >> 3, gg = r & 7;
        int ks = lane >> 3, pr = lane & 7, hi = pr >> 2, tg = pr & 3;
        g_xf[(rt16 * 4 + ks) * 128 + half * 64 + gg * 8 + tg * 2 + hi] =
            pack_bf16x2(d0 * rstd, d1 * rstd);
    }
}

// ---------------- K4: lm head, bf16 mma.sync m16n8k16; B-resident, A frags from g_xf; two-pass ----------------
// Pass A (STORE=false): GEMM + exp + rowsum atomics (no probs store).
// Pass B (STORE=true):  GEMM + exp * (1/rowsum) + store.
#define K4_ROW_ITERS 8

template <bool STORE>
__global__ __launch_bounds__(256, 2) void k4_tc(const float* __restrict__ lmW,
                                                const float* __restrict__ lmb,
                                                float* __restrict__ out) {
    __shared__ uint32_t Bs[4096];
    __shared__ float bsm[128];

    int tid = threadIdx.x;
    int cb = blockIdx.x * 128;

    // B fill: 128 cols x 32 kpairs, bf16x2 words (coalesced over n)
    for (int i = tid; i < 4096; i += 256) {
        int n = i & 127, w = i >> 7;
        float v0 = lmW[(size_t)(2 * w) * VOCAB + cb + n];
        float v1 = lmW[(size_t)(2 * w + 1) * VOCAB + cb + n];
        int nt = n >> 3, gg = n & 7;
        int ks = w >> 3, pr = w & 7, hi = pr >> 2, tg = pr & 3;
        Bs[(nt * 4 + ks) * 64 + gg * 8 + tg * 2 + hi] = pack_bf16x2(v0, v1);
    }
    if (tid < 128) bsm[tid] = lmb[cb + tid];
    __syncthreads();

    int lane = tid & 31, warp = tid >> 5;
    int wm = warp >> 1, wn = warp & 1;
    int g = lane >> 2, tig = lane & 3;

    float2 bv[8];
#pragma unroll
    for (int nt = 0; nt < 8; nt++)
        bv[nt] = *(const float2*)&bsm[wn * 64 + nt * 8 + 2 * tig];

#pragma unroll 1
    for (int it = 0; it < K4_ROW_ITERS; it++) {
        int rb = (blockIdx.y * K4_ROW_ITERS + it) * 128;
        int rt16b = rb >> 4;

        float acc[2][8][4];
#pragma unroll
        for (int mt = 0; mt < 2; mt++)
#pragma unroll
            for (int nt = 0; nt < 8; nt++)
#pragma unroll
                for (int j = 0; j < 4; j++) acc[mt][nt][j] = 0.f;

#pragma unroll
        for (int ks = 0; ks < 4; ks++) {
            uint32_t a[2][4];
#pragma unroll
            for (int mt = 0; mt < 2; mt++) {
                const uint32_t* ap = g_xf + ((rt16b + wm * 2 + mt) * 4 + ks) * 128;
                uint2 p0 = __ldg((const uint2*)(ap + lane * 2));
                uint2 p1 = __ldg((const uint2*)(ap + 64 + lane * 2));
                a[mt][0] = p0.x; a[mt][2] = p0.y; a[mt][1] = p1.x; a[mt][3] = p1.y;
            }
#pragma unroll
            for (int nt = 0; nt < 8; nt++) {
                const uint32_t* bp = Bs + ((wn * 8 + nt) * 4 + ks) * 64;
                uint2 bb = *(const uint2*)(bp + lane * 2);
#pragma unroll
                for (int mt = 0; mt < 2; mt++) {
                    asm volatile(
                        "mma.sync.aligned.m16n8k16.row.col.f32.bf16.bf16.f32 "
                        "{%0,%1,%2,%3}, {%4,%5,%6,%7}, {%8,%9}, {%0,%1,%2,%3};\n"
                        : "+f"(acc[mt][nt][0]), "+f"(acc[mt][nt][1]),
                          "+f"(acc[mt][nt][2]), "+f"(acc[mt][nt][3])
                        : "r"(a[mt][0]), "r"(a[mt][1]), "r"(a[mt][2]), "r"(a[mt][3]),
                          "r"(bb.x), "r"(bb.y));
                }
            }
        }

#pragma unroll
        for (int mt = 0; mt < 2; mt++) {
            int r_lo = rb + wm * 32 + mt * 16 + g;
            if (STORE) {
                float inv_lo = 1.f / g_rowsum[r_lo];
                float inv_hi = 1.f / g_rowsum[r_lo + 8];
                float* plo = out + (size_t)LBL_OFF + (size_t)r_lo * VOCAB + cb + wn * 64 + 2 * tig;
                float* phi = plo + (size_t)8 * VOCAB;
#pragma unroll
                for (int nt = 0; nt < 8; nt++) {
                    float e0 = __expf(acc[mt][nt][0] + bv[nt].x) * inv_lo;
                    float e1 = __expf(acc[mt][nt][1] + bv[nt].y) * inv_lo;
                    float e2 = __expf(acc[mt][nt][2] + bv[nt].x) * inv_hi;
                    float e3 = __expf(acc[mt][nt][3] + bv[nt].y) * inv_hi;
                    *(float2*)(plo + nt * 8) = make_float2(e0, e1);
                    *(float2*)(phi + nt * 8) = make_float2(e2, e3);
                }
            } else {
                float slo = 0.f, shi = 0.f;
#pragma unroll
                for (int nt = 0; nt < 8; nt++) {
                    slo += __expf(acc[mt][nt][0] + bv[nt].x) + __expf(acc[mt][nt][1] + bv[nt].y);
                    shi += __expf(acc[mt][nt][2] + bv[nt].x) + __expf(acc[mt][nt][3] + bv[nt].y);
                }
                slo += __shfl_xor_sync(0xffffffffu, slo, 1);
                slo += __shfl_xor_sync(0xffffffffu, slo, 2);
                shi += __shfl_xor_sync(0xffffffffu, shi, 1);
                shi += __shfl_xor_sync(0xffffffffu, shi, 2);
                if (tig == 0) {
                    atomicAdd(&g_rowsum[r_lo], slo);
                    atomicAdd(&g_rowsum[r_lo + 8], shi);
                }
            }
        }
    }
}

// ---------------- K6: labels ----------------
__global__ void k6_labels(const int* __restrict__ edge_tokens, float* __restrict__ out) {
    int idx = blockIdx.x * 256 + threadIdx.x;
    if (idx < N_EDGES * L_TOK) {
        int e = idx >> 3;
        int tok = edge_tokens[idx];
        int lab = (e == 0 && tok >= 4) ? tok : -100;
        out[idx] = (float)lab;
    }
}

// ---------------- launch ----------------
extern "C" void kernel_launch(void* const* d_in, const int* in_sizes, int n_in,
                              void* d_out, int out_size) {
    const int*   node_tokens = (const int*)d_in[0];
    const int*   edge_tokens = (const int*)d_in[1];
    const int*   edge_index  = (const int*)d_in[2];
    const float* emb    = (const float*)d_in[3];
    const float* W_self = (const float*)d_in[4];
    const float* W_nbr  = (const float*)d_in[5];
    const float* Wq     = (const float*)d_in[6];
    const float* Wk     = (const float*)d_in[7];
    const float* Wv     = (const float*)d_in[8];
    const float* Wo     = (const float*)d_in[9];
    const float* W1     = (const float*)d_in[10];
    const float* W2     = (const float*)d_in[11];
    const float* lmW    = (const float*)d_in[12];
    const float* lmb    = (const float*)d_in[13];
    float* out = (float*)d_out;

    k0_zero<<<2080, 128>>>(edge_index);
    k1_msg<<<128, 128>>>(node_tokens, edge_tokens, edge_index, emb, W_nbr);
    k3_fused<<<512, 256>>>(node_tokens, edge_index, emb, W_self,
                           Wq, Wk, Wv, Wo, W1, W2);
    k4_tc<false><<<dim3(250, 4), 256>>>(lmW, lmb, out);
    k4_tc<true><<<dim3(250, 4), 256>>>(lmW, lmb, out);
    k6_labels<<<64, 256>>>(edge_tokens, out);
}

// round 11
// speedup vs baseline: 1.9880x; 1.2472x over previous
#include <cuda_runtime.h>
#include <cuda_bf16.h>
#include <cstdint>

#define N_NODES 100000
#define N_EDGES 2048
#define L_TOK 8
#define HID 64
#define D_IN 512      // L_TOK * HID
#define D_GNN 128
#define VOCAB 32000
#define FFN_D 256
#define NROWS (N_EDGES * 2)   // 4096 lm-head rows
#define LBL_OFF 16384         // labels occupy [0, 16384)

// ---------------- device scratch (no allocations allowed) ----------------
// Invariant: g_agg (touched rows) and g_rowsum are ZERO at kernel_launch entry.
// Statically zero-initialized; re-zeroed by k6_fin at the end of every call.
__device__ float g_agg[N_NODES * D_GNN];
__device__ uint32_t g_xf[256 * 4 * 128];          // x in bf16x2 fragment-major
__device__ float g_rowsum[NROWS];

__device__ __forceinline__ uint32_t pack_bf16x2(float lo, float hi) {
    __nv_bfloat162 b = __float22bfloat162_rn(make_float2(lo, hi));
    return *(uint32_t*)&b;
}

// ---------------- K1: msg = (node_emb[src] + edge_emb) @ W_nbr; scatter-add at dst ----------------
// 256 blocks x 8 edges, 256 threads; thread group p handles 4 edges for col c.
#define K1_EDGES 8
__global__ __launch_bounds__(256) void k1_msg(const int* __restrict__ node_tokens,
                                              const int* __restrict__ edge_tokens,
                                              const int* __restrict__ edge_index,
                                              const float* __restrict__ emb,
                                              const float* __restrict__ W_nbr) {
    __shared__ float t_s[K1_EDGES][D_IN];
    __shared__ int s_src[K1_EDGES], s_dst[K1_EDGES];
    int b = blockIdx.x, tid = threadIdx.x;
    int e0 = b * K1_EDGES;
    if (tid < K1_EDGES) {
        s_src[tid] = edge_index[e0 + tid];
        s_dst[tid] = edge_index[N_EDGES + e0 + tid];
    }
    __syncthreads();
    for (int idx = tid; idx < K1_EDGES * D_IN; idx += 256) {
        int el = idx >> 9, kk = idx & 511;
        int l = kk >> 6, h = kk & 63;
        int tn = node_tokens[s_src[el] * L_TOK + l];
        int te = edge_tokens[(e0 + el) * L_TOK + l];
        t_s[el][kk] = emb[tn * HID + h] + emb[te * HID + h];
    }
    __syncthreads();
    int c = tid & 127, p = tid >> 7;   // p in {0,1}: edges 4p..4p+3
    float a0 = 0.f, a1 = 0.f, a2 = 0.f, a3 = 0.f;
    const float* t0 = t_s[4 * p + 0];
    const float* t1 = t_s[4 * p + 1];
    const float* t2 = t_s[4 * p + 2];
    const float* t3 = t_s[4 * p + 3];
#pragma unroll 8
    for (int k = 0; k < D_IN; k++) {
        float w = W_nbr[k * D_GNN + c];
        a0 += t0[k] * w;
        a1 += t1[k] * w;
        a2 += t2[k] * w;
        a3 += t3[k] * w;
    }
    atomicAdd(&g_agg[s_dst[4 * p + 0] * D_GNN + c], a0);
    atomicAdd(&g_agg[s_dst[4 * p + 1] * D_GNN + c], a1);
    atomicAdd(&g_agg[s_dst[4 * p + 2] * D_GNN + c], a2);
    atomicAdd(&g_agg[s_dst[4 * p + 3] * D_GNN + c], a3);
}

// ---------------- K3: fused GNN-h + transformer; 2 edges/block, 128 threads ----------------
__global__ __launch_bounds__(128) void k3_fused(const int* __restrict__ node_tokens,
                                                const int* __restrict__ edge_index,
                                                const float* __restrict__ emb,
                                                const float* __restrict__ W_self,
                                                const float* __restrict__ Wq, const float* __restrict__ Wk,
                                                const float* __restrict__ Wv, const float* __restrict__ Wo,
                                                const float* __restrict__ W1, const float* __restrict__ W2) {
    __shared__ float ne[4][D_IN];      // 8 KB
    __shared__ float hn[4][D_GNN];     // 2 KB
    __shared__ int snode[4];
    __shared__ float xsm[4][64];
    __shared__ float ksm[2][2][64];
    __shared__ float vsm[2][2][64];
    __shared__ float hsm[4][FFN_D];    // 4 KB

    int tid = threadIdx.x, lane = tid & 31, wid = tid >> 5;
    int e_base = blockIdx.x * 2;

    if (tid < 4)
        snode[tid] = edge_index[(tid & 1) * N_EDGES + e_base + (tid >> 1)];
    __syncthreads();

    for (int idx = tid; idx < 4 * D_IN; idx += 128) {
        int j = idx >> 9, kk = idx & 511;
        int l = kk >> 6, hcol = kk & 63;
        int tok = node_tokens[snode[j] * L_TOK + l];
        ne[j][kk] = emb[tok * HID + hcol];
    }
    __syncthreads();

    // h = relu(emb @ W_self + agg): thread owns col c for all 4 endpoint nodes
    {
        int c = tid;
        float acc0 = 0.f, acc1 = 0.f, acc2 = 0.f, acc3 = 0.f;
        const float4* n0 = (const float4*)ne[0];
        const float4* n1 = (const float4*)ne[1];
        const float4* n2 = (const float4*)ne[2];
        const float4* n3 = (const float4*)ne[3];
#pragma unroll 4
        for (int k4i = 0; k4i < D_IN / 4; k4i++) {
            float4 a = n0[k4i], b = n1[k4i], cc = n2[k4i], d = n3[k4i];
            const float* wr = W_self + k4i * 4 * D_GNN + c;
            float w0 = wr[0], w1 = wr[D_GNN], w2 = wr[2 * D_GNN], w3 = wr[3 * D_GNN];
            acc0 += a.x * w0 + a.y * w1 + a.z * w2 + a.w * w3;
            acc1 += b.x * w0 + b.y * w1 + b.z * w2 + b.w * w3;
            acc2 += cc.x * w0 + cc.y * w1 + cc.z * w2 + cc.w * w3;
            acc3 += d.x * w0 + d.y * w1 + d.z * w2 + d.w * w3;
        }
        hn[0][c] = fmaxf(acc0 + g_agg[snode[0] * D_GNN + c], 0.f);
        hn[1][c] = fmaxf(acc1 + g_agg[snode[1] * D_GNN + c], 0.f);
        hn[2][c] = fmaxf(acc2 + g_agg[snode[2] * D_GNN + c], 0.f);
        hn[3][c] = fmaxf(acc3 + g_agg[snode[3] * D_GNN + c], 0.f);
    }
    __syncthreads();

    // transformer: warp per (edge el = wid>>1, seq s = wid&1)
    int el = wid >> 1, s = wid & 1;
    int e = e_base + el;

    const float2* hs2 = (const float2*)&hn[2 * el][s * 64];
    const float2* hd2 = (const float2*)&hn[2 * el + 1][s * 64];
    float2 xa2 = hs2[lane], xb2 = hd2[lane];
    float x0 = xa2.x + xb2.x, x1 = xa2.y + xb2.y;
    xsm[wid][2 * lane] = x0;
    xsm[wid][2 * lane + 1] = x1;
    __syncwarp();

    const float2* Wq2 = (const float2*)Wq;
    const float2* Wk2 = (const float2*)Wk;
    const float2* Wv2 = (const float2*)Wv;
    const float2* Wo2 = (const float2*)Wo;
    const float2* W22 = (const float2*)W2;

    float q0 = 0.f, q1 = 0.f, kk0 = 0.f, kk1 = 0.f, v0 = 0.f, v1 = 0.f;
    float q0b = 0.f, q1b = 0.f, kk0b = 0.f, kk1b = 0.f, v0b = 0.f, v1b = 0.f;
#pragma unroll
    for (int k = 0; k < 64; k += 2) {
        float xa = xsm[wid][k], xb = xsm[wid][k + 1];
        float2 wqa = Wq2[k * 32 + lane], wqb = Wq2[(k + 1) * 32 + lane];
        float2 wka = Wk2[k * 32 + lane], wkb = Wk2[(k + 1) * 32 + lane];
        float2 wva = Wv2[k * 32 + lane], wvb = Wv2[(k + 1) * 32 + lane];
        q0 += xa * wqa.x; q1 += xa * wqa.y;
        kk0 += xa * wka.x; kk1 += xa * wka.y;
        v0 += xa * wva.x; v1 += xa * wva.y;
        q0b += xb * wqb.x; q1b += xb * wqb.y;
        kk0b += xb * wkb.x; kk1b += xb * wkb.y;
        v0b += xb * wvb.x; v1b += xb * wvb.y;
    }
    q0 += q0b; q1 += q1b; kk0 += kk0b; kk1 += kk1b; v0 += v0b; v1 += v1b;
    ksm[el][s][2 * lane] = kk0; ksm[el][s][2 * lane + 1] = kk1;
    vsm[el][s][2 * lane] = v0;  vsm[el][s][2 * lane + 1] = v1;
    __syncthreads();

    float p0 = q0 * ksm[el][0][2 * lane] + q1 * ksm[el][0][2 * lane + 1];
    float p1 = q0 * ksm[el][1][2 * lane] + q1 * ksm[el][1][2 * lane + 1];
#pragma unroll
    for (int d = 16; d; d >>= 1) {
        p0 += __shfl_xor_sync(0xffffffffu, p0, d);
        p1 += __shfl_xor_sync(0xffffffffu, p1, d);
    }
    p0 *= 0.125f; p1 *= 0.125f;
    float m = fmaxf(p0, p1);
    float ea = __expf(p0 - m), eb = __expf(p1 - m);
    float inv = 1.f / (ea + eb);
    float a0 = ea * inv, a1 = eb * inv;

    float y0 = a0 * vsm[el][0][2 * lane]     + a1 * vsm[el][1][2 * lane];
    float y1 = a0 * vsm[el][0][2 * lane + 1] + a1 * vsm[el][1][2 * lane + 1];

    xsm[wid][2 * lane] = y0;
    xsm[wid][2 * lane + 1] = y1;
    __syncwarp();

    float o0 = 0.f, o1 = 0.f, o0b = 0.f, o1b = 0.f;
#pragma unroll
    for (int k = 0; k < 64; k += 2) {
        float ya = xsm[wid][k], yb = xsm[wid][k + 1];
        float2 woa = Wo2[k * 32 + lane], wob = Wo2[(k + 1) * 32 + lane];
        o0 += ya * woa.x; o1 += ya * woa.y;
        o0b += yb * wob.x; o1b += yb * wob.y;
    }
    x0 += o0 + o0b; x1 += o1 + o1b;

    float msum = x0 + x1;
#pragma unroll
    for (int d = 16; d; d >>= 1) msum += __shfl_xor_sync(0xffffffffu, msum, d);
    float mean = msum * (1.f / 64.f);
    float d0 = x0 - mean, d1 = x1 - mean;
    float vsum = d0 * d0 + d1 * d1;
#pragma unroll
    for (int d = 16; d; d >>= 1) vsum += __shfl_xor_sync(0xffffffffu, vsum, d);
    float rstd = rsqrtf(vsum * (1.f / 64.f) + 1e-5f);
    x0 = d0 * rstd; x1 = d1 * rstd;

    __syncwarp();
    xsm[wid][2 * lane] = x0;
    xsm[wid][2 * lane + 1] = x1;
    __syncwarp();

    float h[8];
#pragma unroll
    for (int j = 0; j < 8; j++) h[j] = 0.f;
#pragma unroll 8
    for (int k = 0; k < 64; k++) {
        float xk = xsm[wid][k];
        const float* w1r = W1 + k * FFN_D + lane;
#pragma unroll
        for (int j = 0; j < 8; j++) h[j] += xk * w1r[j * 32];
    }
#pragma unroll
    for (int j = 0; j < 8; j++) hsm[wid][j * 32 + lane] = fmaxf(h[j], 0.f);
    __syncwarp();

    float o20 = 0.f, o21 = 0.f, o20b = 0.f, o21b = 0.f;
#pragma unroll 8
    for (int f = 0; f < FFN_D; f += 2) {
        float ha = hsm[wid][f], hb = hsm[wid][f + 1];
        float2 w2a = W22[f * 32 + lane], w2b = W22[(f + 1) * 32 + lane];
        o20 += ha * w2a.x; o21 += ha * w2a.y;
        o20b += hb * w2b.x; o21b += hb * w2b.y;
    }
    float z0 = x0 + o20 + o20b, z1 = x1 + o21 + o21b;

    msum = z0 + z1;
#pragma unroll
    for (int d = 16; d; d >>= 1) msum += __shfl_xor_sync(0xffffffffu, msum, d);
    mean = msum * (1.f / 64.f);
    d0 = z0 - mean; d1 = z1 - mean;
    vsum = d0 * d0 + d1 * d1;
#pragma unroll
    for (int d = 16; d; d >>= 1) vsum += __shfl_xor_sync(0xffffffffu, vsum, d);
    rstd = rsqrtf(vsum * (1.f / 64.f) + 1e-5f);

    // store bf16x2 fragment-major: row r = e*2+s, lane owns kpair w=lane
    {
        int r = e * 2 + s;
        int rt16 = r >> 4, half = (r & 15) >> 3, gg = r & 7;
        int ks = lane >> 3, pr = lane & 7, hi = pr >> 2, tg = pr & 3;
        g_xf[(rt16 * 4 + ks) * 128 + half * 64 + gg * 8 + tg * 2 + hi] =
            pack_bf16x2(d0 * rstd, d1 * rstd);
    }
}

// ---------------- K4: lm head, bf16 mma.sync m16n8k16; B-resident; two-pass ----------------
#define K4_ROW_ITERS 8

template <bool STORE>
__global__ __launch_bounds__(256, 2) void k4_tc(const float* __restrict__ lmW,
                                                const float* __restrict__ lmb,
                                                float* __restrict__ out) {
    __shared__ uint32_t Bs[4096];
    __shared__ float bsm[128];

    int tid = threadIdx.x;
    int cb = blockIdx.x * 128;

    for (int i = tid; i < 4096; i += 256) {
        int n = i & 127, w = i >> 7;
        float v0 = lmW[(size_t)(2 * w) * VOCAB + cb + n];
        float v1 = lmW[(size_t)(2 * w + 1) * VOCAB + cb + n];
        int nt = n >> 3, gg = n & 7;
        int ks = w >> 3, pr = w & 7, hi = pr >> 2, tg = pr & 3;
        Bs[(nt * 4 + ks) * 64 + gg * 8 + tg * 2 + hi] = pack_bf16x2(v0, v1);
    }
    if (tid < 128) bsm[tid] = lmb[cb + tid];
    __syncthreads();

    int lane = tid & 31, warp = tid >> 5;
    int wm = warp >> 1, wn = warp & 1;
    int g = lane >> 2, tig = lane & 3;

    float2 bv[8];
#pragma unroll
    for (int nt = 0; nt < 8; nt++)
        bv[nt] = *(const float2*)&bsm[wn * 64 + nt * 8 + 2 * tig];

#pragma unroll 1
    for (int it = 0; it < K4_ROW_ITERS; it++) {
        int rb = (blockIdx.y * K4_ROW_ITERS + it) * 128;
        int rt16b = rb >> 4;

        float acc[2][8][4];
#pragma unroll
        for (int mt = 0; mt < 2; mt++)
#pragma unroll
            for (int nt = 0; nt < 8; nt++)
#pragma unroll
                for (int j = 0; j < 4; j++) acc[mt][nt][j] = 0.f;

#pragma unroll
        for (int ks = 0; ks < 4; ks++) {
            uint32_t a[2][4];
#pragma unroll
            for (int mt = 0; mt < 2; mt++) {
                const uint32_t* ap = g_xf + ((rt16b + wm * 2 + mt) * 4 + ks) * 128;
                uint2 p0 = __ldg((const uint2*)(ap + lane * 2));
                uint2 p1 = __ldg((const uint2*)(ap + 64 + lane * 2));
                a[mt][0] = p0.x; a[mt][2] = p0.y; a[mt][1] = p1.x; a[mt][3] = p1.y;
            }
#pragma unroll
            for (int nt = 0; nt < 8; nt++) {
                const uint32_t* bp = Bs + ((wn * 8 + nt) * 4 + ks) * 64;
                uint2 bb = *(const uint2*)(bp + lane * 2);
#pragma unroll
                for (int mt = 0; mt < 2; mt++) {
                    asm volatile(
                        "mma.sync.aligned.m16n8k16.row.col.f32.bf16.bf16.f32 "
                        "{%0,%1,%2,%3}, {%4,%5,%6,%7}, {%8,%9}, {%0,%1,%2,%3};\n"
                        : "+f"(acc[mt][nt][0]), "+f"(acc[mt][nt][1]),
                          "+f"(acc[mt][nt][2]), "+f"(acc[mt][nt][3])
                        : "r"(a[mt][0]), "r"(a[mt][1]), "r"(a[mt][2]), "r"(a[mt][3]),
                          "r"(bb.x), "r"(bb.y));
                }
            }
        }

#pragma unroll
        for (int mt = 0; mt < 2; mt++) {
            int r_lo = rb + wm * 32 + mt * 16 + g;
            if (STORE) {
                float inv_lo = 1.f / g_rowsum[r_lo];
                float inv_hi = 1.f / g_rowsum[r_lo + 8];
                float* plo = out + (size_t)LBL_OFF + (size_t)r_lo * VOCAB + cb + wn * 64 + 2 * tig;
                float* phi = plo + (size_t)8 * VOCAB;
#pragma unroll
                for (int nt = 0; nt < 8; nt++) {
                    float e0 = __expf(acc[mt][nt][0] + bv[nt].x) * inv_lo;
                    float e1 = __expf(acc[mt][nt][1] + bv[nt].y) * inv_lo;
                    float e2 = __expf(acc[mt][nt][2] + bv[nt].x) * inv_hi;
                    float e3 = __expf(acc[mt][nt][3] + bv[nt].y) * inv_hi;
                    *(float2*)(plo + nt * 8) = make_float2(e0, e1);
                    *(float2*)(phi + nt * 8) = make_float2(e2, e3);
                }
            } else {
                float slo = 0.f, shi = 0.f;
#pragma unroll
                for (int nt = 0; nt < 8; nt++) {
                    slo += __expf(acc[mt][nt][0] + bv[nt].x) + __expf(acc[mt][nt][1] + bv[nt].y);
                    shi += __expf(acc[mt][nt][2] + bv[nt].x) + __expf(acc[mt][nt][3] + bv[nt].y);
                }
                slo += __shfl_xor_sync(0xffffffffu, slo, 1);
                slo += __shfl_xor_sync(0xffffffffu, slo, 2);
                shi += __shfl_xor_sync(0xffffffffu, shi, 1);
                shi += __shfl_xor_sync(0xffffffffu, shi, 2);
                if (tig == 0) {
                    atomicAdd(&g_rowsum[r_lo], slo);
                    atomicAdd(&g_rowsum[r_lo + 8], shi);
                }
            }
        }
    }
}

// ---------------- K6: labels + restore zero-invariant for g_agg / g_rowsum ----------------
// blocks [0,2048): zero g_agg dst rows; [2048,2080): zero g_rowsum; [2080,2208): labels.
__global__ void k6_fin(const int* __restrict__ edge_tokens,
                       const int* __restrict__ edge_index,
                       float* __restrict__ out) {
    int b = blockIdx.x, t = threadIdx.x;
    if (b < N_EDGES) {
        int dst = edge_index[N_EDGES + b];
        g_agg[dst * D_GNN + t] = 0.f;
    } else if (b < N_EDGES + 32) {
        g_rowsum[(b - N_EDGES) * 128 + t] = 0.f;
    } else {
        int idx = (b - N_EDGES - 32) * 128 + t;
        int e = idx >> 3;
        int tok = edge_tokens[idx];
        out[idx] = (float)((e == 0 && tok >= 4) ? tok : -100);
    }
}

// ---------------- launch ----------------
extern "C" void kernel_launch(void* const* d_in, const int* in_sizes, int n_in,
                              void* d_out, int out_size) {
    const int*   node_tokens = (const int*)d_in[0];
    const int*   edge_tokens = (const int*)d_in[1];
    const int*   edge_index  = (const int*)d_in[2];
    const float* emb    = (const float*)d_in[3];
    const float* W_self = (const float*)d_in[4];
    const float* W_nbr  = (const float*)d_in[5];
    const float* Wq     = (const float*)d_in[6];
    const float* Wk     = (const float*)d_in[7];
    const float* Wv     = (const float*)d_in[8];
    const float* Wo     = (const float*)d_in[9];
    const float* W1     = (const float*)d_in[10];
    const float* W2     = (const float*)d_in[11];
    const float* lmW    = (const float*)d_in[12];
    const float* lmb    = (const float*)d_in[13];
    float* out = (float*)d_out;

    k1_msg<<<N_EDGES / K1_EDGES, 256>>>(node_tokens, edge_tokens, edge_index, emb, W_nbr);
    k3_fused<<<N_EDGES / 2, 128>>>(node_tokens, edge_index, emb, W_self,
                                   Wq, Wk, Wv, Wo, W1, W2);
    k4_tc<false><<<dim3(250, 4), 256>>>(lmW, lmb, out);
    k4_tc<true><<<dim3(250, 4), 256>>>(lmW, lmb, out);
    k6_fin<<<N_EDGES + 32 + 128, 128>>>(edge_tokens, edge_index, out);
}

// round 12
// speedup vs baseline: 2.6021x; 1.3089x over previous
#include <cuda_runtime.h>
#include <cuda_bf16.h>
#include <cstdint>

#define N_NODES 100000
#define N_EDGES 2048
#define L_TOK 8
#define HID 64
#define D_IN 512      // L_TOK * HID
#define D_GNN 128
#define VOCAB 32000
#define FFN_D 256
#define NROWS (N_EDGES * 2)   // 4096 lm-head rows
#define LBL_OFF 16384         // labels occupy [0, 16384)

// ---------------- device scratch (no allocations allowed) ----------------
// Invariant: g_agg (touched rows) and g_rowsum are ZERO at kernel_launch entry.
// Statically zero-initialized; re-zeroed by k6_fin at the end of every call.
__device__ float g_agg[N_NODES * D_GNN];
__device__ uint32_t g_xf[256 * 4 * 128];          // x in bf16x2 fragment-major
__device__ float g_rowsum[NROWS];

__device__ __forceinline__ uint32_t pack_bf16x2(float lo, float hi) {
    __nv_bfloat162 b = __float22bfloat162_rn(make_float2(lo, hi));
    return *(uint32_t*)&b;
}

// ---------------- K1: msg = (node_emb[src] + edge_emb) @ W_nbr; scatter-add at dst ----------------
#define K1_EDGES 8
__global__ __launch_bounds__(256) void k1_msg(const int* __restrict__ node_tokens,
                                              const int* __restrict__ edge_tokens,
                                              const int* __restrict__ edge_index,
                                              const float* __restrict__ emb,
                                              const float* __restrict__ W_nbr) {
    __shared__ float t_s[K1_EDGES][D_IN];
    __shared__ int s_src[K1_EDGES], s_dst[K1_EDGES];
    int b = blockIdx.x, tid = threadIdx.x;
    int e0 = b * K1_EDGES;
    if (tid < K1_EDGES) {
        s_src[tid] = edge_index[e0 + tid];
        s_dst[tid] = edge_index[N_EDGES + e0 + tid];
    }
    __syncthreads();
    for (int idx = tid; idx < K1_EDGES * D_IN; idx += 256) {
        int el = idx >> 9, kk = idx & 511;
        int l = kk >> 6, h = kk & 63;
        int tn = node_tokens[s_src[el] * L_TOK + l];
        int te = edge_tokens[(e0 + el) * L_TOK + l];
        t_s[el][kk] = emb[tn * HID + h] + emb[te * HID + h];
    }
    __syncthreads();
    int c = tid & 127, p = tid >> 7;
    float a0 = 0.f, a1 = 0.f, a2 = 0.f, a3 = 0.f;
    const float* t0 = t_s[4 * p + 0];
    const float* t1 = t_s[4 * p + 1];
    const float* t2 = t_s[4 * p + 2];
    const float* t3 = t_s[4 * p + 3];
#pragma unroll 8
    for (int k = 0; k < D_IN; k++) {
        float w = W_nbr[k * D_GNN + c];
        a0 += t0[k] * w;
        a1 += t1[k] * w;
        a2 += t2[k] * w;
        a3 += t3[k] * w;
    }
    atomicAdd(&g_agg[s_dst[4 * p + 0] * D_GNN + c], a0);
    atomicAdd(&g_agg[s_dst[4 * p + 1] * D_GNN + c], a1);
    atomicAdd(&g_agg[s_dst[4 * p + 2] * D_GNN + c], a2);
    atomicAdd(&g_agg[s_dst[4 * p + 3] * D_GNN + c], a3);
}

// ---------------- K3: fused GNN-h + transformer; WARP PER EDGE (2 rows/warp) ----------------
// 4 edges/block (4 warps, 128 threads), 512 blocks. Each weight load feeds both seq rows.
__global__ __launch_bounds__(128) void k3_fused(const int* __restrict__ node_tokens,
                                                const int* __restrict__ edge_index,
                                                const float* __restrict__ emb,
                                                const float* __restrict__ W_self,
                                                const float* __restrict__ Wq, const float* __restrict__ Wk,
                                                const float* __restrict__ Wv, const float* __restrict__ Wo,
                                                const float* __restrict__ W1, const float* __restrict__ W2) {
    __shared__ float ne[8][D_IN];        // 16 KB: 8 endpoint nodes
    __shared__ float hn[8][D_GNN];       // 4 KB
    __shared__ int snode[8];
    __shared__ float xsm[4][2][64];      // 2 KB broadcast stage
    __shared__ float hsm[4][2][FFN_D];   // 8 KB FFN activations

    int tid = threadIdx.x, lane = tid & 31, wid = tid >> 5;
    int e_base = blockIdx.x * 4;

    // node j: edge j>>1, side j&1 (0=src, 1=dst)
    if (tid < 8)
        snode[tid] = edge_index[(tid & 1) * N_EDGES + e_base + (tid >> 1)];
    __syncthreads();

    for (int idx = tid; idx < 8 * D_IN; idx += 128) {
        int j = idx >> 9, kk = idx & 511;
        int l = kk >> 6, hcol = kk & 63;
        int tok = node_tokens[snode[j] * L_TOK + l];
        ne[j][kk] = emb[tok * HID + hcol];
    }
    __syncthreads();

    // GNN h: thread owns col c for all 8 endpoint nodes
    {
        int c = tid;
        float acc[8];
#pragma unroll
        for (int j = 0; j < 8; j++) acc[j] = 0.f;
#pragma unroll 2
        for (int k4i = 0; k4i < D_IN / 4; k4i++) {
            const float* wr = W_self + k4i * 4 * D_GNN + c;
            float w0 = wr[0], w1 = wr[D_GNN], w2 = wr[2 * D_GNN], w3 = wr[3 * D_GNN];
#pragma unroll
            for (int j = 0; j < 8; j++) {
                float4 a = ((const float4*)ne[j])[k4i];
                acc[j] += a.x * w0 + a.y * w1 + a.z * w2 + a.w * w3;
            }
        }
#pragma unroll
        for (int j = 0; j < 8; j++)
            hn[j][c] = fmaxf(acc[j] + g_agg[snode[j] * D_GNN + c], 0.f);
    }
    __syncthreads();

    // ---- transformer: warp wid owns edge e, BOTH seq rows ----
    int e = e_base + wid;
    float2 s0a = ((const float2*)&hn[2 * wid][0])[lane];
    float2 s0b = ((const float2*)&hn[2 * wid + 1][0])[lane];
    float2 s1a = ((const float2*)&hn[2 * wid][64])[lane];
    float2 s1b = ((const float2*)&hn[2 * wid + 1][64])[lane];
    float x00 = s0a.x + s0b.x, x01 = s0a.y + s0b.y;   // s=0, cols 2lane, 2lane+1
    float x10 = s1a.x + s1b.x, x11 = s1a.y + s1b.y;   // s=1
    xsm[wid][0][2 * lane] = x00; xsm[wid][0][2 * lane + 1] = x01;
    xsm[wid][1][2 * lane] = x10; xsm[wid][1][2 * lane + 1] = x11;
    __syncwarp();

    const float2* Wq2 = (const float2*)Wq;
    const float2* Wk2 = (const float2*)Wk;
    const float2* Wv2 = (const float2*)Wv;
    const float2* Wo2 = (const float2*)Wo;
    const float2* W22 = (const float2*)W2;

    // QKV: 12 accumulators (2 rows x {q,k,v} x 2 cols)
    float q00 = 0.f, q01 = 0.f, k00 = 0.f, k01 = 0.f, v00 = 0.f, v01 = 0.f;
    float q10 = 0.f, q11 = 0.f, k10 = 0.f, k11 = 0.f, v10 = 0.f, v11 = 0.f;
#pragma unroll 4
    for (int k = 0; k < 64; k++) {
        float xa = xsm[wid][0][k], xb = xsm[wid][1][k];
        float2 wq = Wq2[k * 32 + lane];
        float2 wk = Wk2[k * 32 + lane];
        float2 wv = Wv2[k * 32 + lane];
        q00 += xa * wq.x; q01 += xa * wq.y; q10 += xb * wq.x; q11 += xb * wq.y;
        k00 += xa * wk.x; k01 += xa * wk.y; k10 += xb * wk.x; k11 += xb * wk.y;
        v00 += xa * wv.x; v01 += xa * wv.y; v10 += xb * wv.x; v11 += xb * wv.y;
    }

    // scores: all warp-local
    float p00 = q00 * k00 + q01 * k01;
    float p01 = q00 * k10 + q01 * k11;
    float p10 = q10 * k00 + q11 * k01;
    float p11 = q10 * k10 + q11 * k11;
#pragma unroll
    for (int d = 16; d; d >>= 1) {
        p00 += __shfl_xor_sync(0xffffffffu, p00, d);
        p01 += __shfl_xor_sync(0xffffffffu, p01, d);
        p10 += __shfl_xor_sync(0xffffffffu, p10, d);
        p11 += __shfl_xor_sync(0xffffffffu, p11, d);
    }
    p00 *= 0.125f; p01 *= 0.125f; p10 *= 0.125f; p11 *= 0.125f;
    float m0 = fmaxf(p00, p01), m1 = fmaxf(p10, p11);
    float e00 = __expf(p00 - m0), e01 = __expf(p01 - m0);
    float e10 = __expf(p10 - m1), e11 = __expf(p11 - m1);
    float i0 = 1.f / (e00 + e01), i1 = 1.f / (e10 + e11);
    float a00 = e00 * i0, a01 = e01 * i0;
    float a10 = e10 * i1, a11 = e11 * i1;

    float y00 = a00 * v00 + a01 * v10, y01 = a00 * v01 + a01 * v11;
    float y10 = a10 * v00 + a11 * v10, y11 = a10 * v01 + a11 * v11;

    xsm[wid][0][2 * lane] = y00; xsm[wid][0][2 * lane + 1] = y01;
    xsm[wid][1][2 * lane] = y10; xsm[wid][1][2 * lane + 1] = y11;
    __syncwarp();

    // @Wo + residual
    float o00 = 0.f, o01 = 0.f, o10 = 0.f, o11 = 0.f;
#pragma unroll 4
    for (int k = 0; k < 64; k++) {
        float ya = xsm[wid][0][k], yb = xsm[wid][1][k];
        float2 wo = Wo2[k * 32 + lane];
        o00 += ya * wo.x; o01 += ya * wo.y;
        o10 += yb * wo.x; o11 += yb * wo.y;
    }
    x00 += o00; x01 += o01; x10 += o10; x11 += o11;

    // LN1 (both rows)
    float ms0 = x00 + x01, ms1 = x10 + x11;
#pragma unroll
    for (int d = 16; d; d >>= 1) {
        ms0 += __shfl_xor_sync(0xffffffffu, ms0, d);
        ms1 += __shfl_xor_sync(0xffffffffu, ms1, d);
    }
    float mean0 = ms0 * (1.f / 64.f), mean1 = ms1 * (1.f / 64.f);
    float d00 = x00 - mean0, d01 = x01 - mean0;
    float d10 = x10 - mean1, d11 = x11 - mean1;
    float vs0 = d00 * d00 + d01 * d01, vs1 = d10 * d10 + d11 * d11;
#pragma unroll
    for (int d = 16; d; d >>= 1) {
        vs0 += __shfl_xor_sync(0xffffffffu, vs0, d);
        vs1 += __shfl_xor_sync(0xffffffffu, vs1, d);
    }
    float r0 = rsqrtf(vs0 * (1.f / 64.f) + 1e-5f);
    float r1 = rsqrtf(vs1 * (1.f / 64.f) + 1e-5f);
    x00 = d00 * r0; x01 = d01 * r0;
    x10 = d10 * r1; x11 = d11 * r1;

    __syncwarp();
    xsm[wid][0][2 * lane] = x00; xsm[wid][0][2 * lane + 1] = x01;
    xsm[wid][1][2 * lane] = x10; xsm[wid][1][2 * lane + 1] = x11;
    __syncwarp();

    // FFN up: 16 accumulators (2 rows x 8 f-cols)
    float h[2][8];
#pragma unroll
    for (int j = 0; j < 8; j++) { h[0][j] = 0.f; h[1][j] = 0.f; }
#pragma unroll 4
    for (int k = 0; k < 64; k++) {
        float xa = xsm[wid][0][k], xb = xsm[wid][1][k];
        const float* w1r = W1 + k * FFN_D + lane;
#pragma unroll
        for (int j = 0; j < 8; j++) {
            float w = w1r[j * 32];
            h[0][j] += xa * w;
            h[1][j] += xb * w;
        }
    }
#pragma unroll
    for (int j = 0; j < 8; j++) {
        hsm[wid][0][j * 32 + lane] = fmaxf(h[0][j], 0.f);
        hsm[wid][1][j * 32 + lane] = fmaxf(h[1][j], 0.f);
    }
    __syncwarp();

    // FFN down + residual
    float o200 = 0.f, o201 = 0.f, o210 = 0.f, o211 = 0.f;
#pragma unroll 8
    for (int f = 0; f < FFN_D; f++) {
        float ha = hsm[wid][0][f], hb = hsm[wid][1][f];
        float2 w2 = W22[f * 32 + lane];
        o200 += ha * w2.x; o201 += ha * w2.y;
        o210 += hb * w2.x; o211 += hb * w2.y;
    }
    float z00 = x00 + o200, z01 = x01 + o201;
    float z10 = x10 + o210, z11 = x11 + o211;

    // LN2 (both rows)
    ms0 = z00 + z01; ms1 = z10 + z11;
#pragma unroll
    for (int d = 16; d; d >>= 1) {
        ms0 += __shfl_xor_sync(0xffffffffu, ms0, d);
        ms1 += __shfl_xor_sync(0xffffffffu, ms1, d);
    }
    mean0 = ms0 * (1.f / 64.f); mean1 = ms1 * (1.f / 64.f);
    d00 = z00 - mean0; d01 = z01 - mean0;
    d10 = z10 - mean1; d11 = z11 - mean1;
    vs0 = d00 * d00 + d01 * d01; vs1 = d10 * d10 + d11 * d11;
#pragma unroll
    for (int d = 16; d; d >>= 1) {
        vs0 += __shfl_xor_sync(0xffffffffu, vs0, d);
        vs1 += __shfl_xor_sync(0xffffffffu, vs1, d);
    }
    r0 = rsqrtf(vs0 * (1.f / 64.f) + 1e-5f);
    r1 = rsqrtf(vs1 * (1.f / 64.f) + 1e-5f);

    // store bf16x2 fragment-major for both rows; lane owns kpair w=lane
    {
        int ks = lane >> 3, pr = lane & 7, hi = pr >> 2, tg = pr & 3;
        int frag = ks * 128 + tg * 2 + hi;
#pragma unroll
        for (int s = 0; s < 2; s++) {
            int rr = e * 2 + s;
            int rt16 = rr >> 4, half = (rr & 15) >> 3, gg = rr & 7;
            float lo = (s == 0 ? d00 * r0 : d10 * r1);
            float hi2 = (s == 0 ? d01 * r0 : d11 * r1);
            g_xf[rt16 * 512 + frag + half * 64 + gg * 8] = pack_bf16x2(lo, hi2);
        }
    }
}

// ---------------- K4: lm head, bf16 mma.sync m16n8k16; B-resident; two-pass ----------------
#define K4_ROW_ITERS 8

template <bool STORE>
__global__ __launch_bounds__(256, 2) void k4_tc(const float* __restrict__ lmW,
                                                const float* __restrict__ lmb,
                                                float* __restrict__ out) {
    __shared__ uint32_t Bs[4096];
    __shared__ float bsm[128];

    int tid = threadIdx.x;
    int cb = blockIdx.x * 128;

    for (int i = tid; i < 4096; i += 256) {
        int n = i & 127, w = i >> 7;
        float v0 = lmW[(size_t)(2 * w) * VOCAB + cb + n];
        float v1 = lmW[(size_t)(2 * w + 1) * VOCAB + cb + n];
        int nt = n >> 3, gg = n & 7;
        int ks = w >> 3, pr = w & 7, hi = pr >> 2, tg = pr & 3;
        Bs[(nt * 4 + ks) * 64 + gg * 8 + tg * 2 + hi] = pack_bf16x2(v0, v1);
    }
    if (tid < 128) bsm[tid] = lmb[cb + tid];
    __syncthreads();

    int lane = tid & 31, warp = tid >> 5;
    int wm = warp >> 1, wn = warp & 1;
    int g = lane >> 2, tig = lane & 3;

    float2 bv[8];
#pragma unroll
    for (int nt = 0; nt < 8; nt++)
        bv[nt] = *(const float2*)&bsm[wn * 64 + nt * 8 + 2 * tig];

#pragma unroll 1
    for (int it = 0; it < K4_ROW_ITERS; it++) {
        int rb = (blockIdx.y * K4_ROW_ITERS + it) * 128;
        int rt16b = rb >> 4;

        float acc[2][8][4];
#pragma unroll
        for (int mt = 0; mt < 2; mt++)
#pragma unroll
            for (int nt = 0; nt < 8; nt++)
#pragma unroll
                for (int j = 0; j < 4; j++) acc[mt][nt][j] = 0.f;

#pragma unroll
        for (int ks = 0; ks < 4; ks++) {
            uint32_t a[2][4];
#pragma unroll
            for (int mt = 0; mt < 2; mt++) {
                const uint32_t* ap = g_xf + ((rt16b + wm * 2 + mt) * 4 + ks) * 128;
                uint2 p0 = __ldg((const uint2*)(ap + lane * 2));
                uint2 p1 = __ldg((const uint2*)(ap + 64 + lane * 2));
                a[mt][0] = p0.x; a[mt][2] = p0.y; a[mt][1] = p1.x; a[mt][3] = p1.y;
            }
#pragma unroll
            for (int nt = 0; nt < 8; nt++) {
                const uint32_t* bp = Bs + ((wn * 8 + nt) * 4 + ks) * 64;
                uint2 bb = *(const uint2*)(bp + lane * 2);
#pragma unroll
                for (int mt = 0; mt < 2; mt++) {
                    asm volatile(
                        "mma.sync.aligned.m16n8k16.row.col.f32.bf16.bf16.f32 "
                        "{%0,%1,%2,%3}, {%4,%5,%6,%7}, {%8,%9}, {%0,%1,%2,%3};\n"
                        : "+f"(acc[mt][nt][0]), "+f"(acc[mt][nt][1]),
                          "+f"(acc[mt][nt][2]), "+f"(acc[mt][nt][3])
                        : "r"(a[mt][0]), "r"(a[mt][1]), "r"(a[mt][2]), "r"(a[mt][3]),
                          "r"(bb.x), "r"(bb.y));
                }
            }
        }

#pragma unroll
        for (int mt = 0; mt < 2; mt++) {
            int r_lo = rb + wm * 32 + mt * 16 + g;
            if (STORE) {
                float inv_lo = 1.f / g_rowsum[r_lo];
                float inv_hi = 1.f / g_rowsum[r_lo + 8];
                float* plo = out + (size_t)LBL_OFF + (size_t)r_lo * VOCAB + cb + wn * 64 + 2 * tig;
                float* phi = plo + (size_t)8 * VOCAB;
#pragma unroll
                for (int nt = 0; nt < 8; nt++) {
                    float e0 = __expf(acc[mt][nt][0] + bv[nt].x) * inv_lo;
                    float e1 = __expf(acc[mt][nt][1] + bv[nt].y) * inv_lo;
                    float e2 = __expf(acc[mt][nt][2] + bv[nt].x) * inv_hi;
                    float e3 = __expf(acc[mt][nt][3] + bv[nt].y) * inv_hi;
                    __stcs((float2*)(plo + nt * 8), make_float2(e0, e1));
                    __stcs((float2*)(phi + nt * 8), make_float2(e2, e3));
                }
            } else {
                float slo = 0.f, shi = 0.f;
#pragma unroll
                for (int nt = 0; nt < 8; nt++) {
                    slo += __expf(acc[mt][nt][0] + bv[nt].x) + __expf(acc[mt][nt][1] + bv[nt].y);
                    shi += __expf(acc[mt][nt][2] + bv[nt].x) + __expf(acc[mt][nt][3] + bv[nt].y);
                }
                slo += __shfl_xor_sync(0xffffffffu, slo, 1);
                slo += __shfl_xor_sync(0xffffffffu, slo, 2);
                shi += __shfl_xor_sync(0xffffffffu, shi, 1);
                shi += __shfl_xor_sync(0xffffffffu, shi, 2);
                if (tig == 0) {
                    atomicAdd(&g_rowsum[r_lo], slo);
                    atomicAdd(&g_rowsum[r_lo + 8], shi);
                }
            }
        }
    }
}

// ---------------- K6: labels + restore zero-invariant for g_agg / g_rowsum ----------------
__global__ void k6_fin(const int* __restrict__ edge_tokens,
                       const int* __restrict__ edge_index,
                       float* __restrict__ out) {
    int b = blockIdx.x, t = threadIdx.x;
    if (b < N_EDGES) {
        int dst = edge_index[N_EDGES + b];
        g_agg[dst * D_GNN + t] = 0.f;
    } else if (b < N_EDGES + 32) {
        g_rowsum[(b - N_EDGES) * 128 + t] = 0.f;
    } else {
        int idx = (b - N_EDGES - 32) * 128 + t;
        int e = idx >> 3;
        int tok = edge_tokens[idx];
        out[idx] = (float)((e == 0 && tok >= 4) ? tok : -100);
    }
}

// ---------------- launch ----------------
extern "C" void kernel_launch(void* const* d_in, const int* in_sizes, int n_in,
                              void* d_out, int out_size) {
    const int*   node_tokens = (const int*)d_in[0];
    const int*   edge_tokens = (const int*)d_in[1];
    const int*   edge_index  = (const int*)d_in[2];
    const float* emb    = (const float*)d_in[3];
    const float* W_self = (const float*)d_in[4];
    const float* W_nbr  = (const float*)d_in[5];
    const float* Wq     = (const float*)d_in[6];
    const float* Wk     = (const float*)d_in[7];
    const float* Wv     = (const float*)d_in[8];
    const float* Wo     = (const float*)d_in[9];
    const float* W1     = (const float*)d_in[10];
    const float* W2     = (const float*)d_in[11];
    const float* lmW    = (const float*)d_in[12];
    const float* lmb    = (const float*)d_in[13];
    float* out = (float*)d_out;

    k1_msg<<<N_EDGES / K1_EDGES, 256>>>(node_tokens, edge_tokens, edge_index, emb, W_nbr);
    k3_fused<<<N_EDGES / 4, 128>>>(node_tokens, edge_index, emb, W_self,
                                   Wq, Wk, Wv, Wo, W1, W2);
    k4_tc<false><<<dim3(250, 4), 256>>>(lmW, lmb, out);
    k4_tc<true><<<dim3(250, 4), 256>>>(lmW, lmb, out);
    k6_fin<<<N_EDGES + 32 + 128, 128>>>(edge_tokens, edge_index, out);
}